// round 5
// baseline (speedup 1.0000x reference)
#include <cuda_runtime.h>
#include <cstdint>

// Problem constants
static constexpr int Bn = 4;
static constexpr int Cn = 256;     // channels (value dim)
static constexpr int CQ = 32;      // C/8 (qk dim)
static constexpr int Nn = 4096;    // H*W

// Scratch (static device globals: allocation-free)
__device__ float g_fT[Bn * Nn * CQ];   // keys,    transposed: [b][n][q]
__device__ float g_gT[Bn * Nn * CQ];   // queries, transposed: [b][n][q]
__device__ float g_v [Bn * Cn * Nn];   // values:  [b][c][n]

// ===========================================================================
// tf32 warp MMA: D(16x8) += A(16x8) * B(8x8), row.col
// A frag: a0=(g,t) a1=(g+8,t) a2=(g,t+4) a3=(g+8,t+4)   [g=lane>>2, t=lane&3]
// B frag: b0=(k=t, n=g) b1=(k=t+4, n=g)
// C frag: c0=(g,2t) c1=(g,2t+1) c2=(g+8,2t) c3=(g+8,2t+1)
// ===========================================================================
__device__ __forceinline__ void mma_tf32(float* d,
                                         uint32_t a0, uint32_t a1,
                                         uint32_t a2, uint32_t a3,
                                         uint32_t b0, uint32_t b1) {
    asm volatile(
        "mma.sync.aligned.m16n8k8.row.col.f32.tf32.tf32.f32 "
        "{%0,%1,%2,%3}, {%4,%5,%6,%7}, {%8,%9}, {%0,%1,%2,%3};"
        : "+f"(d[0]), "+f"(d[1]), "+f"(d[2]), "+f"(d[3])
        : "r"(a0), "r"(a1), "r"(a2), "r"(a3), "r"(b0), "r"(b1));
}

// 3xTF32 split helpers: hi = round-to-nearest tf32, lo = residual (hw-truncated)
__device__ __forceinline__ uint32_t f2tf32(float x) {
    uint32_t r;
    asm("cvt.rna.tf32.f32 %0, %1;" : "=r"(r) : "f"(x));
    return r;
}
__device__ __forceinline__ uint32_t tf32lo(float x, uint32_t hi) {
    return __float_as_uint(x - __uint_as_float(hi));
}

// permute a 0..31 k/col index so (x, x+4) land adjacent: 8*(x/8)+2*(x%4)+bit2(x)
__device__ __forceinline__ int perm32(int x) {
    return (x & 24) | ((x & 3) << 1) | ((x >> 2) & 1);
}

// ===========================================================================
// Kernel 1: projections (fp32 CUDA-core GEMM). f,g written TRANSPOSED [n][q].
// ===========================================================================
__global__ __launch_bounds__(256) void proj_kernel(
    const float* __restrict__ x,
    const float* __restrict__ Wq,
    const float* __restrict__ Wk,
    const float* __restrict__ Wv)
{
    __shared__ float Ws[64 * 17];
    __shared__ float xs[16 * 64];

    const int b  = blockIdx.z;
    const int r0 = blockIdx.y * 64;
    const int n0 = blockIdx.x * 64;
    const int tid = threadIdx.x;
    const int tx = tid & 15, ty = tid >> 4;

    const float* xb = x + (size_t)b * Cn * Nn;
    float acc[4][4] = {};

    for (int k0 = 0; k0 < Cn; k0 += 16) {
        #pragma unroll
        for (int t = 0; t < 4; t++) {
            int e  = tid + 256 * t;
            int rr = e >> 4, kk = e & 15;
            int r  = r0 + rr;
            const float* Wsrc; int row;
            if (r < 32)      { Wsrc = Wq; row = r; }
            else if (r < 64) { Wsrc = Wk; row = r - 32; }
            else             { Wsrc = Wv; row = r - 64; }
            Ws[rr * 17 + kk] = Wsrc[row * Cn + k0 + kk];
        }
        #pragma unroll
        for (int t = 0; t < 4; t++) {
            int e  = tid + 256 * t;
            int kk = e >> 6, nn = e & 63;
            xs[kk * 64 + nn] = xb[(size_t)(k0 + kk) * Nn + n0 + nn];
        }
        __syncthreads();

        #pragma unroll
        for (int kk = 0; kk < 16; kk++) {
            float a[4], bb[4];
            #pragma unroll
            for (int i = 0; i < 4; i++) a[i]  = Ws[(ty + 16 * i) * 17 + kk];
            #pragma unroll
            for (int j = 0; j < 4; j++) bb[j] = xs[kk * 64 + tx + 16 * j];
            #pragma unroll
            for (int i = 0; i < 4; i++)
                #pragma unroll
                for (int j = 0; j < 4; j++)
                    acc[i][j] += a[i] * bb[j];
        }
        __syncthreads();
    }

    #pragma unroll
    for (int i = 0; i < 4; i++) {
        int r = r0 + ty + 16 * i;
        #pragma unroll
        for (int j = 0; j < 4; j++) {
            int n = n0 + tx + 16 * j;
            if (r < 32)
                g_fT[(size_t)b * Nn * CQ + (size_t)n * CQ + r] = acc[i][j];
            else if (r < 64)
                g_gT[(size_t)b * Nn * CQ + (size_t)n * CQ + (r - 32)] = acc[i][j];
            else
                g_v [(size_t)b * Cn * Nn + (size_t)(r - 64) * Nn + n] = acc[i][j];
        }
    }
}

// ===========================================================================
// Kernel 2: fused attention, 3xTF32 mma.sync (error-compensated split).
// CTA: batch b, 64 j-columns. 8 warps; warp w owns c-stripe [32w,32w+32) and
// S j-slice [8w,8w+8). i-loop in chunks of 32:
//   MMA1: S[i 0..31][j slice] = f^T g         (K = 32 q)
//   exp -> denom partial (shfl reduce) -> eT[j][i] smem
//   MMA2: acc[c stripe][all 64 j] += v e      (K = 32 i)
// ===========================================================================
static constexpr int JT = 64;
static constexpr int IC = 32;
static constexpr int NITER = Nn / IC;   // 128

// smem float offsets (stride 40 per 32-wide row; conflict-free LDS.64 phases)
static constexpr int OF_F = 0;                   // [32][40] f chunk  [i][perm q]
static constexpr int OF_G = OF_F + 32 * 40;      // [64][40] g tile   [j][perm q]
static constexpr int OF_V = OF_G + 64 * 40;      // [256][40] v chunk [c][perm i]
static constexpr int OF_E = OF_V + 256 * 40;     // [64][40] exp tile [j][perm i]
static constexpr int OF_D = OF_E + 64 * 40;      // [64] denom
static constexpr int SM_FLOATS = OF_D + 64;      // 16704 floats = 66816 B

__global__ __launch_bounds__(256, 2) void attn_mma(float* __restrict__ out)
{
    extern __shared__ float sm[];
    const int tid  = threadIdx.x;
    const int w    = tid >> 5;
    const int lane = tid & 31;
    const int g    = lane >> 2;     // group id (0..7)
    const int t    = lane & 3;      // thread-in-group (0..3)
    const int b    = blockIdx.y;
    const int j0   = blockIdx.x * JT;

    const float* fT = g_fT + (size_t)b * Nn * CQ;
    const float* gT = g_gT + (size_t)b * Nn * CQ;
    const float* vB = g_v  + (size_t)b * Cn * Nn;

    // ---- persistent g tile: gJ[j][perm(q)] -------------------------------
    #pragma unroll
    for (int e = tid; e < JT * 8; e += 256) {
        int r = e >> 3, c4 = e & 7;
        float4 v4 = *(const float4*)&gT[(size_t)(j0 + r) * CQ + c4 * 4];
        float* row = sm + OF_G + r * 40;
        row[perm32(4 * c4 + 0)] = v4.x;
        row[perm32(4 * c4 + 1)] = v4.y;
        row[perm32(4 * c4 + 2)] = v4.z;
        row[perm32(4 * c4 + 3)] = v4.w;
    }

    float o[2][8][4] = {};      // out acc: [mf(c 16-row)][nf(j 8-col)][frag]
    float dacc0 = 0.0f, dacc1 = 0.0f;

    for (int it = 0; it < NITER; it++) {
        const int i0 = it * IC;
        __syncthreads();   // prev iter consumed fS/vS/eT

        // ---- load f chunk: fS[i][perm q] (one float4 per thread) ---------
        {
            int r = tid >> 3, c4 = tid & 7;
            float4 v4 = *(const float4*)&fT[(size_t)(i0 + r) * CQ + c4 * 4];
            float* row = sm + OF_F + r * 40;
            row[perm32(4 * c4 + 0)] = v4.x;
            row[perm32(4 * c4 + 1)] = v4.y;
            row[perm32(4 * c4 + 2)] = v4.z;
            row[perm32(4 * c4 + 3)] = v4.w;
        }
        // ---- load v chunk: vS[c][perm i] ----------------------------------
        #pragma unroll
        for (int e = tid; e < 256 * 8; e += 256) {
            int r = e >> 3, c4 = e & 7;
            float4 v4 = *(const float4*)&vB[(size_t)r * Nn + i0 + c4 * 4];
            float* row = sm + OF_V + r * 40;
            row[perm32(4 * c4 + 0)] = v4.x;
            row[perm32(4 * c4 + 1)] = v4.y;
            row[perm32(4 * c4 + 2)] = v4.z;
            row[perm32(4 * c4 + 3)] = v4.w;
        }
        __syncthreads();

        // ---- MMA1 (3xTF32): S[0:32 i][8w + 0:8 j], K=32 ------------------
        float s[2][4] = {};
        {
            const float* fSb = sm + OF_F;
            const float* gJb = sm + OF_G + (8 * w + g) * 40;
            #pragma unroll
            for (int kk = 0; kk < 4; kk++) {
                float2 bf = *(const float2*)&gJb[8 * kk + 2 * t];
                uint32_t b0h = f2tf32(bf.x), b1h = f2tf32(bf.y);
                uint32_t b0l = tf32lo(bf.x, b0h), b1l = tf32lo(bf.y, b1h);
                #pragma unroll
                for (int mf = 0; mf < 2; mf++) {
                    float2 a02 = *(const float2*)&fSb[(16 * mf + g)     * 40 + 8 * kk + 2 * t];
                    float2 a13 = *(const float2*)&fSb[(16 * mf + g + 8) * 40 + 8 * kk + 2 * t];
                    uint32_t a0h = f2tf32(a02.x), a1h = f2tf32(a13.x);
                    uint32_t a2h = f2tf32(a02.y), a3h = f2tf32(a13.y);
                    uint32_t a0l = tf32lo(a02.x, a0h), a1l = tf32lo(a13.x, a1h);
                    uint32_t a2l = tf32lo(a02.y, a2h), a3l = tf32lo(a13.y, a3h);
                    mma_tf32(s[mf], a0h, a1h, a2h, a3h, b0h, b1h);
                    mma_tf32(s[mf], a0h, a1h, a2h, a3h, b0l, b1l);
                    mma_tf32(s[mf], a0l, a1l, a2l, a3l, b0h, b1h);
                }
            }
        }

        // ---- exp, denom partials, write eT[j][perm i] --------------------
        {
            float p0 = 0.0f, p1 = 0.0f;
            float* eB = sm + OF_E;
            #pragma unroll
            for (int mf = 0; mf < 2; mf++) {
                #pragma unroll
                for (int r = 0; r < 4; r++) {
                    float ev = __expf(s[mf][r] * 0.0625f);
                    int m  = (r >> 1) + 2 * mf;             // i = g + 8m
                    int jj = 8 * w + 2 * t + (r & 1);
                    eB[jj * 40 + 8 * m + 2 * (g & 3) + (g >> 2)] = ev;
                    if (r & 1) p1 += ev; else p0 += ev;
                }
            }
            #pragma unroll
            for (int off = 4; off <= 16; off <<= 1) {
                p0 += __shfl_xor_sync(0xffffffffu, p0, off);
                p1 += __shfl_xor_sync(0xffffffffu, p1, off);
            }
            dacc0 += p0;
            dacc1 += p1;
        }
        __syncthreads();   // eT visible

        // ---- MMA2 (3xTF32): acc[c stripe][64 j] += v e, K=32 -------------
        {
            const float* vSb = sm + OF_V + 32 * w * 40;
            const float* eTb = sm + OF_E;
            #pragma unroll
            for (int kk = 0; kk < 4; kk++) {
                uint32_t ah[2][4], al[2][4];
                #pragma unroll
                for (int mf = 0; mf < 2; mf++) {
                    float2 a02 = *(const float2*)&vSb[(16 * mf + g)     * 40 + 8 * kk + 2 * t];
                    float2 a13 = *(const float2*)&vSb[(16 * mf + g + 8) * 40 + 8 * kk + 2 * t];
                    ah[mf][0] = f2tf32(a02.x);  al[mf][0] = tf32lo(a02.x, ah[mf][0]);
                    ah[mf][1] = f2tf32(a13.x);  al[mf][1] = tf32lo(a13.x, ah[mf][1]);
                    ah[mf][2] = f2tf32(a02.y);  al[mf][2] = tf32lo(a02.y, ah[mf][2]);
                    ah[mf][3] = f2tf32(a13.y);  al[mf][3] = tf32lo(a13.y, ah[mf][3]);
                }
                #pragma unroll
                for (int nf = 0; nf < 8; nf++) {
                    float2 bf = *(const float2*)&eTb[(8 * nf + g) * 40 + 8 * kk + 2 * t];
                    uint32_t b0h = f2tf32(bf.x), b1h = f2tf32(bf.y);
                    uint32_t b0l = tf32lo(bf.x, b0h), b1l = tf32lo(bf.y, b1h);
                    #pragma unroll
                    for (int mf = 0; mf < 2; mf++) {
                        mma_tf32(o[mf][nf], ah[mf][0], ah[mf][1], ah[mf][2], ah[mf][3], b0h, b1h);
                        mma_tf32(o[mf][nf], ah[mf][0], ah[mf][1], ah[mf][2], ah[mf][3], b0l, b1l);
                        mma_tf32(o[mf][nf], al[mf][0], al[mf][1], al[mf][2], al[mf][3], b0h, b1h);
                    }
                }
            }
        }
    }

    // ---- epilogue: denom -> inverse, normalize, store --------------------
    if (lane < 4) {
        sm[OF_D + 8 * w + 2 * lane]     = dacc0;
        sm[OF_D + 8 * w + 2 * lane + 1] = dacc1;
    }
    __syncthreads();
    if (tid < JT) sm[OF_D + tid] = 1.0f / sm[OF_D + tid];
    __syncthreads();

    float* outB = out + (size_t)b * Cn * Nn;
    #pragma unroll
    for (int nf = 0; nf < 8; nf++) {
        float2 inv = *(const float2*)&sm[OF_D + 8 * nf + 2 * t];
        int j = j0 + 8 * nf + 2 * t;
        #pragma unroll
        for (int mf = 0; mf < 2; mf++) {
            int c0 = 32 * w + 16 * mf + g;
            float2 r0 = make_float2(o[mf][nf][0] * inv.x, o[mf][nf][1] * inv.y);
            float2 r1 = make_float2(o[mf][nf][2] * inv.x, o[mf][nf][3] * inv.y);
            *(float2*)&outB[(size_t)c0       * Nn + j] = r0;
            *(float2*)&outB[(size_t)(c0 + 8) * Nn + j] = r1;
        }
    }
}

// ===========================================================================
extern "C" void kernel_launch(void* const* d_in, const int* in_sizes, int n_in,
                              void* d_out, int out_size)
{
    const float* x  = (const float*)d_in[0];
    const float* Wq = (const float*)d_in[1];
    const float* Wk = (const float*)d_in[2];
    const float* Wv = (const float*)d_in[3];
    float* out = (float*)d_out;

    proj_kernel<<<dim3(Nn / 64, 5, Bn), 256>>>(x, Wq, Wk, Wv);

    const int smem_bytes = SM_FLOATS * (int)sizeof(float);   // 66816 B
    cudaFuncSetAttribute(attn_mma,
                         cudaFuncAttributeMaxDynamicSharedMemorySize, smem_bytes);
    attn_mma<<<dim3(Nn / JT, Bn), 256, smem_bytes>>>(out);
}

// round 6
// speedup vs baseline: 1.5819x; 1.5819x over previous
#include <cuda_runtime.h>
#include <cstdint>

static constexpr int Bn = 4, Cn = 256, CQ = 32, Nn = 4096;

// fp32 proj outputs
__device__ float g_fT[Bn * Nn * CQ];   // [b][n][q]
__device__ float g_gT[Bn * Nn * CQ];   // [b][n][q]
__device__ float g_v [Bn * Cn * Nn];   // [b][c][n]
// split bf16 (packed bf16x2 words, pair-slot permuted)
__device__ uint32_t g_fH[262144],  g_fL[262144];    // row=b*4096+n, 16 words
__device__ uint32_t g_gH[262144],  g_gL[262144];
__device__ uint32_t g_vH[2097152], g_vL[2097152];   // row=b*256+c, 2048 words

// ---------------------------------------------------------------------------
__device__ __forceinline__ uint32_t pack2(float hi, float lo) {
    uint32_t r;
    asm("cvt.rn.bf16x2.f32 %0, %1, %2;" : "=r"(r) : "f"(hi), "f"(lo));
    return r;
}
// x0 -> low half (k even), x1 -> high half (k odd)
__device__ __forceinline__ void split2(float x0, float x1, uint32_t& h, uint32_t& l) {
    h = pack2(x1, x0);
    float h0 = __uint_as_float(h << 16);
    float h1 = __uint_as_float(h & 0xffff0000u);
    l = pack2(x1 - h1, x0 - h0);
}
__device__ __forceinline__ void mma_bf16(float* d, uint32_t a0, uint32_t a1,
                                         uint32_t a2, uint32_t a3,
                                         uint32_t b0, uint32_t b1) {
    asm volatile(
        "mma.sync.aligned.m16n8k16.row.col.f32.bf16.bf16.f32 "
        "{%0,%1,%2,%3},{%4,%5,%6,%7},{%8,%9},{%0,%1,%2,%3};"
        : "+f"(d[0]), "+f"(d[1]), "+f"(d[2]), "+f"(d[3])
        : "r"(a0), "r"(a1), "r"(a2), "r"(a3), "r"(b0), "r"(b1));
}
// smem swizzle: rows are 64B; XOR 32B on row bit1
__device__ __forceinline__ uint32_t swz(int row, uint32_t byteInRow) {
    return (uint32_t)(row * 64) + (byteInRow ^ (((uint32_t)(row >> 1) & 1u) << 5));
}

// ===========================================================================
// Kernel 1: projections (fp32). f,g transposed [n][q].
// ===========================================================================
__global__ __launch_bounds__(256) void proj_kernel(
    const float* __restrict__ x, const float* __restrict__ Wq,
    const float* __restrict__ Wk, const float* __restrict__ Wv)
{
    __shared__ float Ws[64 * 17];
    __shared__ float xs[16 * 64];
    const int b = blockIdx.z, r0 = blockIdx.y * 64, n0 = blockIdx.x * 64;
    const int tid = threadIdx.x, tx = tid & 15, ty = tid >> 4;
    const float* xb = x + (size_t)b * Cn * Nn;
    float acc[4][4] = {};

    for (int k0 = 0; k0 < Cn; k0 += 16) {
        #pragma unroll
        for (int t = 0; t < 4; t++) {
            int e = tid + 256 * t, rr = e >> 4, kk = e & 15, r = r0 + rr;
            const float* Wsrc; int row;
            if (r < 32)      { Wsrc = Wq; row = r; }
            else if (r < 64) { Wsrc = Wk; row = r - 32; }
            else             { Wsrc = Wv; row = r - 64; }
            Ws[rr * 17 + kk] = Wsrc[row * Cn + k0 + kk];
        }
        #pragma unroll
        for (int t = 0; t < 4; t++) {
            int e = tid + 256 * t, kk = e >> 6, nn = e & 63;
            xs[kk * 64 + nn] = xb[(size_t)(k0 + kk) * Nn + n0 + nn];
        }
        __syncthreads();
        #pragma unroll
        for (int kk = 0; kk < 16; kk++) {
            float a[4], bb[4];
            #pragma unroll
            for (int i = 0; i < 4; i++) a[i]  = Ws[(ty + 16 * i) * 17 + kk];
            #pragma unroll
            for (int j = 0; j < 4; j++) bb[j] = xs[kk * 64 + tx + 16 * j];
            #pragma unroll
            for (int i = 0; i < 4; i++)
                #pragma unroll
                for (int j = 0; j < 4; j++) acc[i][j] += a[i] * bb[j];
        }
        __syncthreads();
    }
    #pragma unroll
    for (int i = 0; i < 4; i++) {
        int r = r0 + ty + 16 * i;
        #pragma unroll
        for (int j = 0; j < 4; j++) {
            int n = n0 + tx + 16 * j;
            if (r < 32)      g_fT[(size_t)b*Nn*CQ + (size_t)n*CQ + r]        = acc[i][j];
            else if (r < 64) g_gT[(size_t)b*Nn*CQ + (size_t)n*CQ + (r - 32)] = acc[i][j];
            else             g_v [(size_t)b*Cn*Nn + (size_t)(r - 64)*Nn + n] = acc[i][j];
        }
    }
}

// ===========================================================================
// Kernel 1.5: split fp32 -> bf16 hi/lo, pair-slot permuted.
// storage word w in chunk: kk=w>>3, slot=w&7; source word w8=((slot&1)<<2)|(slot>>1)
// ===========================================================================
__global__ __launch_bounds__(256) void repack_kernel()
{
    int u = blockIdx.x * 256 + threadIdx.x;
    uint32_t h, l;
    if (u < 262144) {
        int row = u >> 4, wd = u & 15;
        int kk = wd >> 3, s = wd & 7, w8 = ((s & 1) << 2) | (s >> 1);
        const float* src = g_fT + (size_t)row * 32 + kk * 16 + w8 * 2;
        split2(src[0], src[1], h, l);
        g_fH[u] = h; g_fL[u] = l;
    } else if (u < 524288) {
        int v = u - 262144;
        int row = v >> 4, wd = v & 15;
        int kk = wd >> 3, s = wd & 7, w8 = ((s & 1) << 2) | (s >> 1);
        const float* src = g_gT + (size_t)row * 32 + kk * 16 + w8 * 2;
        split2(src[0], src[1], h, l);
        g_gH[v] = h; g_gL[v] = l;
    } else {
        int vv = u - 524288;
        int row = vv >> 11, w11 = vv & 2047;
        int it = w11 >> 4, wd = w11 & 15;
        int kk = wd >> 3, s = wd & 7, w8 = ((s & 1) << 2) | (s >> 1);
        const float* src = g_v + (size_t)row * 4096 + it * 32 + kk * 16 + w8 * 2;
        split2(src[0], src[1], h, l);
        g_vH[vv] = h; g_vL[vv] = l;
    }
}

// ===========================================================================
// Kernel 2: fused attention, 3-term split-bf16 m16n8k16.
// CTA: (j-tile 64, batch). 8 warps: MMA1 warp (jb=w&3, ih=w>>2) computes
// S^T[16j x 16i]; exp->pack->e hi/lo smem; MMA2 warp w owns c-stripe 32w.
// ===========================================================================
static constexpr int OF_FH = 0,     OF_FL = 2048;
static constexpr int OF_GH = 4096,  OF_GL = 8192;
static constexpr int OF_VH = 12288, OF_VL = 28672;
static constexpr int OF_EH = 45056, OF_EL = 49152;
static constexpr int OF_DS = 53248, OF_INV = 53760;
static constexpr int SMEM_BYTES = 54016;

__global__ __launch_bounds__(256, 2) void attn_mma(float* __restrict__ out)
{
    extern __shared__ char sm[];
    const int tid = threadIdx.x, w = tid >> 5, lane = tid & 31;
    const int g = lane >> 2, t = lane & 3;
    const int jb = w & 3, ih = w >> 2;
    const int b = blockIdx.y, j0 = blockIdx.x * 64;

    // g tile copy (hi+lo), 1 uint4 each per thread per array
    {
        const uint4* sH = (const uint4*)g_gH + (size_t)(b * 4096 + j0) * 4;
        const uint4* sL = (const uint4*)g_gL + (size_t)(b * 4096 + j0) * 4;
        int r = tid >> 2, q4 = tid & 3;
        *(uint4*)(sm + OF_GH + swz(r, q4 * 16)) = sH[tid];
        *(uint4*)(sm + OF_GL + swz(r, q4 * 16)) = sL[tid];
    }
    __syncthreads();

    // preload g A-fragments (persistent)
    uint2 gah[2][2], gal[2][2];
    #pragma unroll
    for (int kk = 0; kk < 2; kk++) {
        int r0 = 16 * jb + g;
        gah[kk][0] = *(const uint2*)(sm + OF_GH + swz(r0,     kk * 32 + 8 * t));
        gah[kk][1] = *(const uint2*)(sm + OF_GH + swz(r0 + 8, kk * 32 + 8 * t));
        gal[kk][0] = *(const uint2*)(sm + OF_GL + swz(r0,     kk * 32 + 8 * t));
        gal[kk][1] = *(const uint2*)(sm + OF_GL + swz(r0 + 8, kk * 32 + 8 * t));
    }

    float o[2][8][4] = {};
    float d0 = 0.f, d1 = 0.f;

    for (int it = 0; it < 128; it++) {
        __syncthreads();   // prev iter's f/v/e fully consumed

        { // f copy: 128 hi + 128 lo uint4, 1 per thread
            int idx = tid & 127, hl = tid >> 7;
            int r = idx >> 2, q4 = idx & 3;
            const uint4* src = (const uint4*)(hl ? g_fL : g_fH);
            uint4 val = src[(size_t)(b * 4096 + it * 32 + r) * 4 + q4];
            *(uint4*)(sm + (hl ? OF_FL : OF_FH) + swz(r, q4 * 16)) = val;
        }
        #pragma unroll
        for (int k = 0; k < 8; k++) {  // v copy: 1024 hi + 1024 lo uint4
            int e = tid + 256 * k;
            int hl = e >> 10, idx = e & 1023;
            int r = idx >> 2, q4 = idx & 3;
            const uint4* src = (const uint4*)(hl ? g_vL : g_vH);
            uint4 val = src[(size_t)(b * 256 + r) * 512 + it * 4 + q4];
            *(uint4*)(sm + (hl ? OF_VL : OF_VH) + swz(r, q4 * 16)) = val;
        }
        __syncthreads();

        // ---- MMA1: S^T[j 16jb..+16][i 16ih..+16] -------------------------
        float s[2][4] = {};
        #pragma unroll
        for (int kk = 0; kk < 2; kk++) {
            #pragma unroll
            for (int nt = 0; nt < 2; nt++) {
                int fr = 16 * ih + 8 * nt + g;
                uint2 fh = *(const uint2*)(sm + OF_FH + swz(fr, kk * 32 + 8 * t));
                uint2 fl = *(const uint2*)(sm + OF_FL + swz(fr, kk * 32 + 8 * t));
                mma_bf16(s[nt], gah[kk][0].x, gah[kk][1].x, gah[kk][0].y, gah[kk][1].y, fh.x, fh.y);
                mma_bf16(s[nt], gah[kk][0].x, gah[kk][1].x, gah[kk][0].y, gah[kk][1].y, fl.x, fl.y);
                mma_bf16(s[nt], gal[kk][0].x, gal[kk][1].x, gal[kk][0].y, gal[kk][1].y, fh.x, fh.y);
            }
        }
        // ---- exp, denom, pack e hi/lo to smem ----------------------------
        #pragma unroll
        for (int nt = 0; nt < 2; nt++) {
            float e0 = __expf(s[nt][0] * 0.0625f), e1 = __expf(s[nt][1] * 0.0625f);
            float e2 = __expf(s[nt][2] * 0.0625f), e3 = __expf(s[nt][3] * 0.0625f);
            d0 += e0 + e1;  d1 += e2 + e3;
            uint32_t h01, l01, h23, l23;
            split2(e0, e1, h01, l01);
            split2(e2, e3, h23, l23);
            uint32_t byte = (uint32_t)(ih * 32 + (2 * t + nt) * 4);
            int r0 = 16 * jb + g;
            *(uint32_t*)(sm + OF_EH + swz(r0,     byte)) = h01;
            *(uint32_t*)(sm + OF_EL + swz(r0,     byte)) = l01;
            *(uint32_t*)(sm + OF_EH + swz(r0 + 8, byte)) = h23;
            *(uint32_t*)(sm + OF_EL + swz(r0 + 8, byte)) = l23;
        }
        __syncthreads();

        // ---- MMA2: o[c stripe 32w][64 j] += v e, K=32 --------------------
        #pragma unroll
        for (int kk = 0; kk < 2; kk++) {
            uint2 vh[2][2], vl[2][2];
            #pragma unroll
            for (int mf = 0; mf < 2; mf++) {
                int r0 = 32 * w + 16 * mf + g;
                vh[mf][0] = *(const uint2*)(sm + OF_VH + swz(r0,     kk * 32 + 8 * t));
                vh[mf][1] = *(const uint2*)(sm + OF_VH + swz(r0 + 8, kk * 32 + 8 * t));
                vl[mf][0] = *(const uint2*)(sm + OF_VL + swz(r0,     kk * 32 + 8 * t));
                vl[mf][1] = *(const uint2*)(sm + OF_VL + swz(r0 + 8, kk * 32 + 8 * t));
            }
            #pragma unroll
            for (int nf = 0; nf < 8; nf++) {
                int er = 8 * nf + g;
                uint2 eh = *(const uint2*)(sm + OF_EH + swz(er, kk * 32 + 8 * t));
                uint2 el = *(const uint2*)(sm + OF_EL + swz(er, kk * 32 + 8 * t));
                #pragma unroll
                for (int mf = 0; mf < 2; mf++) {
                    mma_bf16(o[mf][nf], vh[mf][0].x, vh[mf][1].x, vh[mf][0].y, vh[mf][1].y, eh.x, eh.y);
                    mma_bf16(o[mf][nf], vh[mf][0].x, vh[mf][1].x, vh[mf][0].y, vh[mf][1].y, el.x, el.y);
                    mma_bf16(o[mf][nf], vl[mf][0].x, vl[mf][1].x, vl[mf][0].y, vl[mf][1].y, eh.x, eh.y);
                }
            }
        }
    }

    // ---- denom reduce (t lanes, then ih warps) ---------------------------
    d0 += __shfl_xor_sync(~0u, d0, 1); d0 += __shfl_xor_sync(~0u, d0, 2);
    d1 += __shfl_xor_sync(~0u, d1, 1); d1 += __shfl_xor_sync(~0u, d1, 2);
    float* dS = (float*)(sm + OF_DS);
    if (t == 0) {
        dS[ih * 64 + 16 * jb + g]     = d0;
        dS[ih * 64 + 16 * jb + g + 8] = d1;
    }
    __syncthreads();
    float* invS = (float*)(sm + OF_INV);
    if (tid < 64) invS[tid] = 1.0f / (dS[tid] + dS[64 + tid]);
    __syncthreads();

    // ---- normalize + store ----------------------------------------------
    float* outB = out + (size_t)b * Cn * Nn;
    #pragma unroll
    for (int nf = 0; nf < 8; nf++) {
        float2 inv = *(const float2*)&invS[8 * nf + 2 * t];
        int j = j0 + 8 * nf + 2 * t;
        #pragma unroll
        for (int mf = 0; mf < 2; mf++) {
            int c0 = 32 * w + 16 * mf + g;
            *(float2*)&outB[(size_t)c0 * Nn + j] =
                make_float2(o[mf][nf][0] * inv.x, o[mf][nf][1] * inv.y);
            *(float2*)&outB[(size_t)(c0 + 8) * Nn + j] =
                make_float2(o[mf][nf][2] * inv.x, o[mf][nf][3] * inv.y);
        }
    }
}

// ===========================================================================
extern "C" void kernel_launch(void* const* d_in, const int* in_sizes, int n_in,
                              void* d_out, int out_size)
{
    const float* x  = (const float*)d_in[0];
    const float* Wq = (const float*)d_in[1];
    const float* Wk = (const float*)d_in[2];
    const float* Wv = (const float*)d_in[3];
    float* out = (float*)d_out;

    proj_kernel<<<dim3(Nn / 64, 5, Bn), 256>>>(x, Wq, Wk, Wv);
    repack_kernel<<<10240, 256>>>();

    cudaFuncSetAttribute(attn_mma,
                         cudaFuncAttributeMaxDynamicSharedMemorySize, SMEM_BYTES);
    attn_mma<<<dim3(Nn / 64, Bn), 256, SMEM_BYTES>>>(out);
}

// round 7
// speedup vs baseline: 1.7514x; 1.1072x over previous
#include <cuda_runtime.h>
#include <cstdint>

static constexpr int Bn = 4, Cn = 256, CQ = 32, Nn = 4096;

// fp32 proj outputs
__device__ float g_fT[Bn * Nn * CQ];   // [b][n][q]
__device__ float g_gT[Bn * Nn * CQ];   // [b][n][q]
__device__ float g_v [Bn * Cn * Nn];   // [b][c][n]
// split bf16 (packed bf16x2 words, pair-slot permuted)
__device__ uint32_t g_fH[262144],  g_fL[262144];    // row=b*4096+n, 16 words
__device__ uint32_t g_gH[262144],  g_gL[262144];
__device__ uint32_t g_vH[2097152], g_vL[2097152];   // row=b*256+c, 2048 words

// ---------------------------------------------------------------------------
__device__ __forceinline__ uint32_t pack2(float hi, float lo) {
    uint32_t r;
    asm("cvt.rn.bf16x2.f32 %0, %1, %2;" : "=r"(r) : "f"(hi), "f"(lo));
    return r;
}
__device__ __forceinline__ void split2(float x0, float x1, uint32_t& h, uint32_t& l) {
    h = pack2(x1, x0);
    float h0 = __uint_as_float(h << 16);
    float h1 = __uint_as_float(h & 0xffff0000u);
    l = pack2(x1 - h1, x0 - h0);
}
__device__ __forceinline__ void mma_bf16(float* d, uint32_t a0, uint32_t a1,
                                         uint32_t a2, uint32_t a3,
                                         uint32_t b0, uint32_t b1) {
    asm volatile(
        "mma.sync.aligned.m16n8k16.row.col.f32.bf16.bf16.f32 "
        "{%0,%1,%2,%3},{%4,%5,%6,%7},{%8,%9},{%0,%1,%2,%3};"
        : "+f"(d[0]), "+f"(d[1]), "+f"(d[2]), "+f"(d[3])
        : "r"(a0), "r"(a1), "r"(a2), "r"(a3), "r"(b0), "r"(b1));
}
__device__ __forceinline__ uint32_t swz(int row, uint32_t byteInRow) {
    return (uint32_t)(row * 64) + (byteInRow ^ (((uint32_t)(row >> 1) & 1u) << 5));
}
__device__ __forceinline__ uint32_t smem_u32(const void* p) {
    uint32_t a;
    asm("{ .reg .u64 t; cvta.to.shared.u64 t, %1; cvt.u32.u64 %0, t; }"
        : "=r"(a) : "l"(p));
    return a;
}
__device__ __forceinline__ void cpa16(uint32_t dst, const void* src) {
    asm volatile("cp.async.cg.shared.global [%0], [%1], 16;"
                 :: "r"(dst), "l"(src));
}
#define CPA_COMMIT() asm volatile("cp.async.commit_group;" ::: "memory")
#define CPA_WAIT0()  asm volatile("cp.async.wait_group 0;" ::: "memory")

// ===========================================================================
// Kernel 1: projections (fp32). 64r x 128n tile, 8x4 micro. f,g -> [n][q].
// ===========================================================================
__global__ __launch_bounds__(256) void proj_kernel(
    const float* __restrict__ x, const float* __restrict__ Wq,
    const float* __restrict__ Wk, const float* __restrict__ Wv)
{
    __shared__ float Ws[16 * 68];    // [kk][r], stride 68
    __shared__ float xs[16 * 128];   // [kk][n]
    const int b = blockIdx.z, r0 = blockIdx.y * 64, n0 = blockIdx.x * 128;
    const int tid = threadIdx.x;
    const int tx = tid & 31;         // n: 4 cols at 4*tx
    const int ty = tid >> 5;         // r: 8 rows at 8*ty
    const float* xb = x + (size_t)b * Cn * Nn;

    float acc[8][4] = {};

    for (int k0 = 0; k0 < Cn; k0 += 16) {
        { // W tile: thread -> float4 of one row
            int rr = tid >> 2, k4 = tid & 3, r = r0 + rr;
            const float* Wsrc; int row;
            if (r < 32)      { Wsrc = Wq; row = r; }
            else if (r < 64) { Wsrc = Wk; row = r - 32; }
            else             { Wsrc = Wv; row = r - 64; }
            float4 wv = *(const float4*)&Wsrc[row * Cn + k0 + 4 * k4];
            Ws[(4 * k4 + 0) * 68 + rr] = wv.x;
            Ws[(4 * k4 + 1) * 68 + rr] = wv.y;
            Ws[(4 * k4 + 2) * 68 + rr] = wv.z;
            Ws[(4 * k4 + 3) * 68 + rr] = wv.w;
        }
        #pragma unroll
        for (int k = 0; k < 2; k++) { // x tile: 512 float4
            int idx = tid + 256 * k;
            int kk = idx >> 5, n4 = idx & 31;
            *(float4*)&xs[kk * 128 + 4 * n4] =
                *(const float4*)&xb[(size_t)(k0 + kk) * Nn + n0 + 4 * n4];
        }
        __syncthreads();

        #pragma unroll
        for (int kk = 0; kk < 16; kk++) {
            float4 a0 = *(const float4*)&Ws[kk * 68 + 8 * ty];
            float4 a1 = *(const float4*)&Ws[kk * 68 + 8 * ty + 4];
            float4 bb = *(const float4*)&xs[kk * 128 + 4 * tx];
            float a[8] = {a0.x, a0.y, a0.z, a0.w, a1.x, a1.y, a1.z, a1.w};
            float bv[4] = {bb.x, bb.y, bb.z, bb.w};
            #pragma unroll
            for (int i = 0; i < 8; i++)
                #pragma unroll
                for (int j = 0; j < 4; j++) acc[i][j] += a[i] * bv[j];
        }
        __syncthreads();
    }

    #pragma unroll
    for (int i = 0; i < 8; i++) {
        int r = r0 + 8 * ty + i;
        if (r < 64) {   // f or g: scatter to transposed [n][q]
            float* dst = (r < 32) ? (g_fT + (size_t)b * Nn * CQ + r)
                                  : (g_gT + (size_t)b * Nn * CQ + (r - 32));
            #pragma unroll
            for (int j = 0; j < 4; j++)
                dst[(size_t)(n0 + 4 * tx + j) * CQ] = acc[i][j];
        } else {        // v: row-contiguous float4
            *(float4*)&g_v[(size_t)b * Cn * Nn + (size_t)(r - 64) * Nn + n0 + 4 * tx]
                = make_float4(acc[i][0], acc[i][1], acc[i][2], acc[i][3]);
        }
    }
}

// ===========================================================================
// Kernel 1.5: split fp32 -> bf16 hi/lo, pair-slot permuted.
// ===========================================================================
__global__ __launch_bounds__(256) void repack_kernel()
{
    int u = blockIdx.x * 256 + threadIdx.x;
    uint32_t h, l;
    if (u < 262144) {
        int row = u >> 4, wd = u & 15;
        int kk = wd >> 3, s = wd & 7, w8 = ((s & 1) << 2) | (s >> 1);
        const float* src = g_fT + (size_t)row * 32 + kk * 16 + w8 * 2;
        split2(src[0], src[1], h, l);
        g_fH[u] = h; g_fL[u] = l;
    } else if (u < 524288) {
        int v = u - 262144;
        int row = v >> 4, wd = v & 15;
        int kk = wd >> 3, s = wd & 7, w8 = ((s & 1) << 2) | (s >> 1);
        const float* src = g_gT + (size_t)row * 32 + kk * 16 + w8 * 2;
        split2(src[0], src[1], h, l);
        g_gH[v] = h; g_gL[v] = l;
    } else {
        int vv = u - 524288;
        int row = vv >> 11, w11 = vv & 2047;
        int it = w11 >> 4, wd = w11 & 15;
        int kk = wd >> 3, s = wd & 7, w8 = ((s & 1) << 2) | (s >> 1);
        const float* src = g_v + (size_t)row * 4096 + it * 32 + kk * 16 + w8 * 2;
        split2(src[0], src[1], h, l);
        g_vH[vv] = h; g_vL[vv] = l;
    }
}

// ===========================================================================
// Kernel 2: fused attention, 3-term split-bf16 m16n8k16, cp.async
// double-buffered f/v tiles (copies overlap MMA of previous iteration).
// ===========================================================================
static constexpr uint32_t BUF_SZ = 36864;               // per-buffer bytes
static constexpr uint32_t IN_FH = 0,    IN_FL = 2048;
static constexpr uint32_t IN_VH = 4096, IN_VL = 20480;
static constexpr uint32_t OF_GH = 73728, OF_GL = 77824;
static constexpr uint32_t OF_EH = 81920, OF_EL = 86016;
static constexpr uint32_t OF_DS = 90112, OF_INV = 90624;
static constexpr uint32_t SMEM_BYTES = 90880;

__device__ __forceinline__ void issue_copies(uint32_t sb, uint32_t bufbase,
                                             int b, int it, int tid)
{
    { // f: 1 uint4 per thread (128 hi + 128 lo)
        int idx = tid & 127, hl = tid >> 7;
        int r = idx >> 2, q4 = idx & 3;
        const uint4* src = (const uint4*)(hl ? g_fL : g_fH)
                         + (size_t)(b * 4096 + it * 32 + r) * 4 + q4;
        cpa16(sb + bufbase + (hl ? IN_FL : IN_FH) + swz(r, q4 * 16), src);
    }
    #pragma unroll
    for (int k = 0; k < 8; k++) { // v: 8 uint4 per thread
        int e = tid + 256 * k;
        int hl = e >> 10, idx = e & 1023;
        int r = idx >> 2, q4 = idx & 3;
        const uint4* src = (const uint4*)(hl ? g_vL : g_vH)
                         + (size_t)(b * 256 + r) * 512 + it * 4 + q4;
        cpa16(sb + bufbase + (hl ? IN_VL : IN_VH) + swz(r, q4 * 16), src);
    }
}

__global__ __launch_bounds__(256, 2) void attn_mma(float* __restrict__ out)
{
    extern __shared__ char sm[];
    const uint32_t sb = smem_u32(sm);
    const int tid = threadIdx.x, w = tid >> 5, lane = tid & 31;
    const int g = lane >> 2, t = lane & 3;
    const int jb = w & 3, ih = w >> 2;
    const int b = blockIdx.y, j0 = blockIdx.x * 64;

    // g tile (persistent): plain load once
    {
        const uint4* sH = (const uint4*)g_gH + (size_t)(b * 4096 + j0) * 4;
        const uint4* sL = (const uint4*)g_gL + (size_t)(b * 4096 + j0) * 4;
        int r = tid >> 2, q4 = tid & 3;
        *(uint4*)(sm + OF_GH + swz(r, q4 * 16)) = sH[tid];
        *(uint4*)(sm + OF_GL + swz(r, q4 * 16)) = sL[tid];
    }
    // prologue prefetch for iter 0
    issue_copies(sb, 0, b, 0, tid);
    CPA_COMMIT();
    __syncthreads();

    // preload g A-fragments (persistent)
    uint2 gah[2][2], gal[2][2];
    #pragma unroll
    for (int kk = 0; kk < 2; kk++) {
        int r0 = 16 * jb + g;
        gah[kk][0] = *(const uint2*)(sm + OF_GH + swz(r0,     kk * 32 + 8 * t));
        gah[kk][1] = *(const uint2*)(sm + OF_GH + swz(r0 + 8, kk * 32 + 8 * t));
        gal[kk][0] = *(const uint2*)(sm + OF_GL + swz(r0,     kk * 32 + 8 * t));
        gal[kk][1] = *(const uint2*)(sm + OF_GL + swz(r0 + 8, kk * 32 + 8 * t));
    }

    float o[2][8][4] = {};
    float d0 = 0.f, d1 = 0.f;

    for (int it = 0; it < 128; it++) {
        CPA_WAIT0();           // this thread's copies for iter `it` arrived
        __syncthreads();       // all copies visible; prev MMA2 fully done

        if (it + 1 < 128) {    // prefetch next tile into the other buffer
            issue_copies(sb, ((it + 1) & 1) ? BUF_SZ : 0u, b, it + 1, tid);
            CPA_COMMIT();
        }
        const uint32_t vb = (it & 1) ? BUF_SZ : 0u;

        // ---- MMA1: S^T[j 16jb..+16][i 16ih..+16] -------------------------
        float s[2][4] = {};
        #pragma unroll
        for (int kk = 0; kk < 2; kk++) {
            #pragma unroll
            for (int nt = 0; nt < 2; nt++) {
                int fr = 16 * ih + 8 * nt + g;
                uint2 fh = *(const uint2*)(sm + vb + IN_FH + swz(fr, kk * 32 + 8 * t));
                uint2 fl = *(const uint2*)(sm + vb + IN_FL + swz(fr, kk * 32 + 8 * t));
                mma_bf16(s[nt], gah[kk][0].x, gah[kk][1].x, gah[kk][0].y, gah[kk][1].y, fh.x, fh.y);
                mma_bf16(s[nt], gah[kk][0].x, gah[kk][1].x, gah[kk][0].y, gah[kk][1].y, fl.x, fl.y);
                mma_bf16(s[nt], gal[kk][0].x, gal[kk][1].x, gal[kk][0].y, gal[kk][1].y, fh.x, fh.y);
            }
        }
        // ---- exp, denom, pack e hi/lo to smem ----------------------------
        #pragma unroll
        for (int nt = 0; nt < 2; nt++) {
            float e0 = __expf(s[nt][0] * 0.0625f), e1 = __expf(s[nt][1] * 0.0625f);
            float e2 = __expf(s[nt][2] * 0.0625f), e3 = __expf(s[nt][3] * 0.0625f);
            d0 += e0 + e1;  d1 += e2 + e3;
            uint32_t h01, l01, h23, l23;
            split2(e0, e1, h01, l01);
            split2(e2, e3, h23, l23);
            uint32_t byte = (uint32_t)(ih * 32 + (2 * t + nt) * 4);
            int r0 = 16 * jb + g;
            *(uint32_t*)(sm + OF_EH + swz(r0,     byte)) = h01;
            *(uint32_t*)(sm + OF_EL + swz(r0,     byte)) = l01;
            *(uint32_t*)(sm + OF_EH + swz(r0 + 8, byte)) = h23;
            *(uint32_t*)(sm + OF_EL + swz(r0 + 8, byte)) = l23;
        }
        __syncthreads();

        // ---- MMA2: o[c stripe 32w][64 j] += v e, K=32 --------------------
        #pragma unroll
        for (int kk = 0; kk < 2; kk++) {
            uint2 vh[2][2], vl[2][2];
            #pragma unroll
            for (int mf = 0; mf < 2; mf++) {
                int r0 = 32 * w + 16 * mf + g;
                vh[mf][0] = *(const uint2*)(sm + vb + IN_VH + swz(r0,     kk * 32 + 8 * t));
                vh[mf][1] = *(const uint2*)(sm + vb + IN_VH + swz(r0 + 8, kk * 32 + 8 * t));
                vl[mf][0] = *(const uint2*)(sm + vb + IN_VL + swz(r0,     kk * 32 + 8 * t));
                vl[mf][1] = *(const uint2*)(sm + vb + IN_VL + swz(r0 + 8, kk * 32 + 8 * t));
            }
            #pragma unroll
            for (int nf = 0; nf < 8; nf++) {
                int er = 8 * nf + g;
                uint2 eh = *(const uint2*)(sm + OF_EH + swz(er, kk * 32 + 8 * t));
                uint2 el = *(const uint2*)(sm + OF_EL + swz(er, kk * 32 + 8 * t));
                #pragma unroll
                for (int mf = 0; mf < 2; mf++) {
                    mma_bf16(o[mf][nf], vh[mf][0].x, vh[mf][1].x, vh[mf][0].y, vh[mf][1].y, eh.x, eh.y);
                    mma_bf16(o[mf][nf], vh[mf][0].x, vh[mf][1].x, vh[mf][0].y, vh[mf][1].y, el.x, el.y);
                    mma_bf16(o[mf][nf], vl[mf][0].x, vl[mf][1].x, vl[mf][0].y, vl[mf][1].y, eh.x, eh.y);
                }
            }
        }
    }

    // ---- denom reduce ----------------------------------------------------
    d0 += __shfl_xor_sync(~0u, d0, 1); d0 += __shfl_xor_sync(~0u, d0, 2);
    d1 += __shfl_xor_sync(~0u, d1, 1); d1 += __shfl_xor_sync(~0u, d1, 2);
    float* dS = (float*)(sm + OF_DS);
    if (t == 0) {
        dS[ih * 64 + 16 * jb + g]     = d0;
        dS[ih * 64 + 16 * jb + g + 8] = d1;
    }
    __syncthreads();
    float* invS = (float*)(sm + OF_INV);
    if (tid < 64) invS[tid] = 1.0f / (dS[tid] + dS[64 + tid]);
    __syncthreads();

    // ---- normalize + store ----------------------------------------------
    float* outB = out + (size_t)b * Cn * Nn;
    #pragma unroll
    for (int nf = 0; nf < 8; nf++) {
        float2 inv = *(const float2*)&invS[8 * nf + 2 * t];
        int j = j0 + 8 * nf + 2 * t;
        #pragma unroll
        for (int mf = 0; mf < 2; mf++) {
            int c0 = 32 * w + 16 * mf + g;
            *(float2*)&outB[(size_t)c0 * Nn + j] =
                make_float2(o[mf][nf][0] * inv.x, o[mf][nf][1] * inv.y);
            *(float2*)&outB[(size_t)(c0 + 8) * Nn + j] =
                make_float2(o[mf][nf][2] * inv.x, o[mf][nf][3] * inv.y);
        }
    }
}

// ===========================================================================
extern "C" void kernel_launch(void* const* d_in, const int* in_sizes, int n_in,
                              void* d_out, int out_size)
{
    const float* x  = (const float*)d_in[0];
    const float* Wq = (const float*)d_in[1];
    const float* Wk = (const float*)d_in[2];
    const float* Wv = (const float*)d_in[3];
    float* out = (float*)d_out;

    proj_kernel<<<dim3(Nn / 128, 5, Bn), 256>>>(x, Wq, Wk, Wv);
    repack_kernel<<<10240, 256>>>();

    cudaFuncSetAttribute(attn_mma,
                         cudaFuncAttributeMaxDynamicSharedMemorySize, SMEM_BYTES);
    attn_mma<<<dim3(Nn / 64, Bn), 256, SMEM_BYTES>>>(out);
}

// round 8
// speedup vs baseline: 2.3764x; 1.3568x over previous
#include <cuda_runtime.h>
#include <cuda_fp16.h>
#include <cstdint>

static constexpr int Bn = 4, Cn = 256, CQ = 32, Nn = 4096;

// fp32 proj outputs
__device__ float g_fT[Bn * Nn * CQ];   // [b][n][q]
__device__ float g_gT[Bn * Nn * CQ];   // [b][n][q]
__device__ float g_v [Bn * Cn * Nn];   // [b][c][n]
// fp16 packed (fp16x2 words, pair-slot permuted). f single, g/v hi+lo split.
__device__ uint32_t g_fX[262144];                   // row=b*4096+n, 16 words
__device__ uint32_t g_gH[262144],  g_gL[262144];
__device__ uint32_t g_vH[2097152], g_vL[2097152];   // row=b*256+c, 2048 words

// ---------------------------------------------------------------------------
__device__ __forceinline__ uint32_t packf16(float x0, float x1) {   // x0 -> low
    __half2 h = __floats2half2_rn(x0, x1);
    return *(uint32_t*)&h;
}
__device__ __forceinline__ void splitf16(float x0, float x1,
                                         uint32_t& h, uint32_t& l) {
    __half2 hh = __floats2half2_rn(x0, x1);
    float2 bk = __half22float2(hh);
    __half2 ll = __floats2half2_rn(x0 - bk.x, x1 - bk.y);
    h = *(uint32_t*)&hh;  l = *(uint32_t*)&ll;
}
__device__ __forceinline__ void mma_f16(float* d, uint32_t a0, uint32_t a1,
                                        uint32_t a2, uint32_t a3,
                                        uint32_t b0, uint32_t b1) {
    asm volatile(
        "mma.sync.aligned.m16n8k16.row.col.f32.f16.f16.f32 "
        "{%0,%1,%2,%3},{%4,%5,%6,%7},{%8,%9},{%0,%1,%2,%3};"
        : "+f"(d[0]), "+f"(d[1]), "+f"(d[2]), "+f"(d[3])
        : "r"(a0), "r"(a1), "r"(a2), "r"(a3), "r"(b0), "r"(b1));
}
__device__ __forceinline__ uint32_t swz(int row, uint32_t byteInRow) {
    return (uint32_t)(row * 64) + (byteInRow ^ (((uint32_t)(row >> 1) & 1u) << 5));
}
__device__ __forceinline__ uint32_t smem_u32(const void* p) {
    uint32_t a;
    asm("{ .reg .u64 t; cvta.to.shared.u64 t, %1; cvt.u32.u64 %0, t; }"
        : "=r"(a) : "l"(p));
    return a;
}
__device__ __forceinline__ void cpa16(uint32_t dst, const void* src) {
    asm volatile("cp.async.cg.shared.global [%0], [%1], 16;"
                 :: "r"(dst), "l"(src));
}
#define CPA_COMMIT() asm volatile("cp.async.commit_group;" ::: "memory")
#define CPA_WAIT0()  asm volatile("cp.async.wait_group 0;" ::: "memory")

// ===========================================================================
// Kernel 1: projections (fp32). 64r x 128n tile, 8x4 micro. f,g -> [n][q].
// ===========================================================================
__global__ __launch_bounds__(256) void proj_kernel(
    const float* __restrict__ x, const float* __restrict__ Wq,
    const float* __restrict__ Wk, const float* __restrict__ Wv)
{
    __shared__ float Ws[16 * 68];
    __shared__ float xs[16 * 128];
    const int b = blockIdx.z, r0 = blockIdx.y * 64, n0 = blockIdx.x * 128;
    const int tid = threadIdx.x;
    const int tx = tid & 31, ty = tid >> 5;
    const float* xb = x + (size_t)b * Cn * Nn;

    float acc[8][4] = {};

    for (int k0 = 0; k0 < Cn; k0 += 16) {
        {
            int rr = tid >> 2, k4 = tid & 3, r = r0 + rr;
            const float* Wsrc; int row;
            if (r < 32)      { Wsrc = Wq; row = r; }
            else if (r < 64) { Wsrc = Wk; row = r - 32; }
            else             { Wsrc = Wv; row = r - 64; }
            float4 wv = *(const float4*)&Wsrc[row * Cn + k0 + 4 * k4];
            Ws[(4 * k4 + 0) * 68 + rr] = wv.x;
            Ws[(4 * k4 + 1) * 68 + rr] = wv.y;
            Ws[(4 * k4 + 2) * 68 + rr] = wv.z;
            Ws[(4 * k4 + 3) * 68 + rr] = wv.w;
        }
        #pragma unroll
        for (int k = 0; k < 2; k++) {
            int idx = tid + 256 * k;
            int kk = idx >> 5, n4 = idx & 31;
            *(float4*)&xs[kk * 128 + 4 * n4] =
                *(const float4*)&xb[(size_t)(k0 + kk) * Nn + n0 + 4 * n4];
        }
        __syncthreads();

        #pragma unroll
        for (int kk = 0; kk < 16; kk++) {
            float4 a0 = *(const float4*)&Ws[kk * 68 + 8 * ty];
            float4 a1 = *(const float4*)&Ws[kk * 68 + 8 * ty + 4];
            float4 bb = *(const float4*)&xs[kk * 128 + 4 * tx];
            float a[8] = {a0.x, a0.y, a0.z, a0.w, a1.x, a1.y, a1.z, a1.w};
            float bv[4] = {bb.x, bb.y, bb.z, bb.w};
            #pragma unroll
            for (int i = 0; i < 8; i++)
                #pragma unroll
                for (int j = 0; j < 4; j++) acc[i][j] += a[i] * bv[j];
        }
        __syncthreads();
    }

    #pragma unroll
    for (int i = 0; i < 8; i++) {
        int r = r0 + 8 * ty + i;
        if (r < 64) {
            float* dst = (r < 32) ? (g_fT + (size_t)b * Nn * CQ + r)
                                  : (g_gT + (size_t)b * Nn * CQ + (r - 32));
            #pragma unroll
            for (int j = 0; j < 4; j++)
                dst[(size_t)(n0 + 4 * tx + j) * CQ] = acc[i][j];
        } else {
            *(float4*)&g_v[(size_t)b * Cn * Nn + (size_t)(r - 64) * Nn + n0 + 4 * tx]
                = make_float4(acc[i][0], acc[i][1], acc[i][2], acc[i][3]);
        }
    }
}

// ===========================================================================
// Kernel 1.5: fp32 -> fp16 (f single; g,v hi/lo split), pair-slot permuted.
// ===========================================================================
__global__ __launch_bounds__(256) void repack_kernel()
{
    int u = blockIdx.x * 256 + threadIdx.x;
    if (u < 262144) {
        int row = u >> 4, wd = u & 15;
        int kk = wd >> 3, s = wd & 7, w8 = ((s & 1) << 2) | (s >> 1);
        const float* src = g_fT + (size_t)row * 32 + kk * 16 + w8 * 2;
        g_fX[u] = packf16(src[0], src[1]);
    } else if (u < 524288) {
        int v = u - 262144;
        int row = v >> 4, wd = v & 15;
        int kk = wd >> 3, s = wd & 7, w8 = ((s & 1) << 2) | (s >> 1);
        const float* src = g_gT + (size_t)row * 32 + kk * 16 + w8 * 2;
        uint32_t h, l;
        splitf16(src[0], src[1], h, l);
        g_gH[v] = h; g_gL[v] = l;
    } else {
        int vv = u - 524288;
        int row = vv >> 11, w11 = vv & 2047;
        int it = w11 >> 4, wd = w11 & 15;
        int kk = wd >> 3, s = wd & 7, w8 = ((s & 1) << 2) | (s >> 1);
        const float* src = g_v + (size_t)row * 4096 + it * 32 + kk * 16 + w8 * 2;
        uint32_t h, l;
        splitf16(src[0], src[1], h, l);
        g_vH[vv] = h; g_vL[vv] = l;
    }
}

// ===========================================================================
// Kernel 2: fused attention, 2-term split-fp16 m16n8k16, cp.async
// double-buffered f/v tiles.
//   MMA1: s = (gh + gl) x f          (8 MMAs/warp/iter)
//   MMA2: o += (vh + vl) x e_fp16    (64 MMAs/warp/iter)
// ===========================================================================
static constexpr uint32_t BUF_SZ = 34816;              // f 2KB + vh/vl 32KB
static constexpr uint32_t IN_F = 0, IN_VH = 2048, IN_VL = 18432;
static constexpr uint32_t OF_GH = 69632, OF_GL = 73728;
static constexpr uint32_t OF_E  = 77824;
static constexpr uint32_t OF_DS = 81920, OF_INV = 82432;
static constexpr uint32_t SMEM_BYTES = 82688;

__device__ __forceinline__ void issue_copies(uint32_t sb, uint32_t bufbase,
                                             int b, int it, int tid)
{
    if (tid < 128) {  // f: 128 uint4 (2KB)
        int r = tid >> 2, q4 = tid & 3;
        const uint4* src = (const uint4*)g_fX
                         + (size_t)(b * 4096 + it * 32 + r) * 4 + q4;
        cpa16(sb + bufbase + IN_F + swz(r, q4 * 16), src);
    }
    #pragma unroll
    for (int k = 0; k < 8; k++) { // v: 2048 uint4 (vh+vl)
        int e = tid + 256 * k;
        int hl = e >> 10, idx = e & 1023;
        int r = idx >> 2, q4 = idx & 3;
        const uint4* src = (const uint4*)(hl ? g_vL : g_vH)
                         + (size_t)(b * 256 + r) * 512 + it * 4 + q4;
        cpa16(sb + bufbase + (hl ? IN_VL : IN_VH) + swz(r, q4 * 16), src);
    }
}

__global__ __launch_bounds__(256, 2) void attn_mma(float* __restrict__ out)
{
    extern __shared__ char sm[];
    const uint32_t sb = smem_u32(sm);
    const int tid = threadIdx.x, w = tid >> 5, lane = tid & 31;
    const int g = lane >> 2, t = lane & 3;
    const int jb = w & 3, ih = w >> 2;
    const int b = blockIdx.y, j0 = blockIdx.x * 64;

    // g tile (persistent): plain load once
    {
        const uint4* sH = (const uint4*)g_gH + (size_t)(b * 4096 + j0) * 4;
        const uint4* sL = (const uint4*)g_gL + (size_t)(b * 4096 + j0) * 4;
        int r = tid >> 2, q4 = tid & 3;
        *(uint4*)(sm + OF_GH + swz(r, q4 * 16)) = sH[tid];
        *(uint4*)(sm + OF_GL + swz(r, q4 * 16)) = sL[tid];
    }
    issue_copies(sb, 0, b, 0, tid);
    CPA_COMMIT();
    __syncthreads();

    // preload g A-fragments (persistent)
    uint2 gah[2][2], gal[2][2];
    #pragma unroll
    for (int kk = 0; kk < 2; kk++) {
        int r0 = 16 * jb + g;
        gah[kk][0] = *(const uint2*)(sm + OF_GH + swz(r0,     kk * 32 + 8 * t));
        gah[kk][1] = *(const uint2*)(sm + OF_GH + swz(r0 + 8, kk * 32 + 8 * t));
        gal[kk][0] = *(const uint2*)(sm + OF_GL + swz(r0,     kk * 32 + 8 * t));
        gal[kk][1] = *(const uint2*)(sm + OF_GL + swz(r0 + 8, kk * 32 + 8 * t));
    }

    float o[2][8][4] = {};
    float d0 = 0.f, d1 = 0.f;

    for (int it = 0; it < 128; it++) {
        CPA_WAIT0();
        __syncthreads();

        if (it + 1 < 128) {
            issue_copies(sb, ((it + 1) & 1) ? BUF_SZ : 0u, b, it + 1, tid);
            CPA_COMMIT();
        }
        const uint32_t vb = (it & 1) ? BUF_SZ : 0u;

        // ---- MMA1: S^T[j 16jb..+16][i 16ih..+16], 2-term -----------------
        float s[2][4] = {};
        #pragma unroll
        for (int kk = 0; kk < 2; kk++) {
            #pragma unroll
            for (int nt = 0; nt < 2; nt++) {
                int fr = 16 * ih + 8 * nt + g;
                uint2 fx = *(const uint2*)(sm + vb + IN_F + swz(fr, kk * 32 + 8 * t));
                mma_f16(s[nt], gah[kk][0].x, gah[kk][1].x, gah[kk][0].y, gah[kk][1].y, fx.x, fx.y);
                mma_f16(s[nt], gal[kk][0].x, gal[kk][1].x, gal[kk][0].y, gal[kk][1].y, fx.x, fx.y);
            }
        }
        // ---- exp, denom, pack e (single fp16) to smem --------------------
        #pragma unroll
        for (int nt = 0; nt < 2; nt++) {
            float e0 = __expf(s[nt][0] * 0.0625f), e1 = __expf(s[nt][1] * 0.0625f);
            float e2 = __expf(s[nt][2] * 0.0625f), e3 = __expf(s[nt][3] * 0.0625f);
            d0 += e0 + e1;  d1 += e2 + e3;
            uint32_t byte = (uint32_t)(ih * 32 + (2 * t + nt) * 4);
            int r0 = 16 * jb + g;
            *(uint32_t*)(sm + OF_E + swz(r0,     byte)) = packf16(e0, e1);
            *(uint32_t*)(sm + OF_E + swz(r0 + 8, byte)) = packf16(e2, e3);
        }
        __syncthreads();

        // ---- MMA2: o[c stripe 32w][64 j] += v e, K=32, 2-term ------------
        #pragma unroll
        for (int kk = 0; kk < 2; kk++) {
            uint2 vh[2][2], vl[2][2];
            #pragma unroll
            for (int mf = 0; mf < 2; mf++) {
                int r0 = 32 * w + 16 * mf + g;
                vh[mf][0] = *(const uint2*)(sm + vb + IN_VH + swz(r0,     kk * 32 + 8 * t));
                vh[mf][1] = *(const uint2*)(sm + vb + IN_VH + swz(r0 + 8, kk * 32 + 8 * t));
                vl[mf][0] = *(const uint2*)(sm + vb + IN_VL + swz(r0,     kk * 32 + 8 * t));
                vl[mf][1] = *(const uint2*)(sm + vb + IN_VL + swz(r0 + 8, kk * 32 + 8 * t));
            }
            #pragma unroll
            for (int nf = 0; nf < 8; nf++) {
                int er = 8 * nf + g;
                uint2 ex = *(const uint2*)(sm + OF_E + swz(er, kk * 32 + 8 * t));
                #pragma unroll
                for (int mf = 0; mf < 2; mf++) {
                    mma_f16(o[mf][nf], vh[mf][0].x, vh[mf][1].x, vh[mf][0].y, vh[mf][1].y, ex.x, ex.y);
                    mma_f16(o[mf][nf], vl[mf][0].x, vl[mf][1].x, vl[mf][0].y, vl[mf][1].y, ex.x, ex.y);
                }
            }
        }
    }

    // ---- denom reduce ----------------------------------------------------
    d0 += __shfl_xor_sync(~0u, d0, 1); d0 += __shfl_xor_sync(~0u, d0, 2);
    d1 += __shfl_xor_sync(~0u, d1, 1); d1 += __shfl_xor_sync(~0u, d1, 2);
    float* dS = (float*)(sm + OF_DS);
    if (t == 0) {
        dS[ih * 64 + 16 * jb + g]     = d0;
        dS[ih * 64 + 16 * jb + g + 8] = d1;
    }
    __syncthreads();
    float* invS = (float*)(sm + OF_INV);
    if (tid < 64) invS[tid] = 1.0f / (dS[tid] + dS[64 + tid]);
    __syncthreads();

    // ---- normalize + store ----------------------------------------------
    float* outB = out + (size_t)b * Cn * Nn;
    #pragma unroll
    for (int nf = 0; nf < 8; nf++) {
        float2 inv = *(const float2*)&invS[8 * nf + 2 * t];
        int j = j0 + 8 * nf + 2 * t;
        #pragma unroll
        for (int mf = 0; mf < 2; mf++) {
            int c0 = 32 * w + 16 * mf + g;
            *(float2*)&outB[(size_t)c0 * Nn + j] =
                make_float2(o[mf][nf][0] * inv.x, o[mf][nf][1] * inv.y);
            *(float2*)&outB[(size_t)(c0 + 8) * Nn + j] =
                make_float2(o[mf][nf][2] * inv.x, o[mf][nf][3] * inv.y);
        }
    }
}

// ===========================================================================
extern "C" void kernel_launch(void* const* d_in, const int* in_sizes, int n_in,
                              void* d_out, int out_size)
{
    const float* x  = (const float*)d_in[0];
    const float* Wq = (const float*)d_in[1];
    const float* Wk = (const float*)d_in[2];
    const float* Wv = (const float*)d_in[3];
    float* out = (float*)d_out;

    proj_kernel<<<dim3(Nn / 128, 5, Bn), 256>>>(x, Wq, Wk, Wv);
    repack_kernel<<<10240, 256>>>();

    cudaFuncSetAttribute(attn_mma,
                         cudaFuncAttributeMaxDynamicSharedMemorySize, SMEM_BYTES);
    attn_mma<<<dim3(Nn / 64, Bn), 256, SMEM_BYTES>>>(out);
}

// round 9
// speedup vs baseline: 2.3837x; 1.0031x over previous
#include <cuda_runtime.h>
#include <cuda_fp16.h>
#include <cstdint>

static constexpr int Bn = 4, Cn = 256, CQ = 32, Nn = 4096;

// fp32 proj outputs
__device__ float g_fT[Bn * Nn * CQ];   // [b][n][q]
__device__ float g_gT[Bn * Nn * CQ];   // [b][n][q]
__device__ float g_v [Bn * Cn * Nn];   // [b][c][n]
// fp16 packed (fp16x2 words, pair-slot permuted). f single, g/v hi+lo split.
__device__ uint32_t g_fX[262144];                   // row=b*4096+n, 16 words
__device__ uint32_t g_gH[262144],  g_gL[262144];
__device__ uint32_t g_vH[2097152], g_vL[2097152];   // row=b*256+c, 2048 words

// ---------------------------------------------------------------------------
__device__ __forceinline__ uint32_t packf16(float x0, float x1) {   // x0 -> low
    __half2 h = __floats2half2_rn(x0, x1);
    return *(uint32_t*)&h;
}
__device__ __forceinline__ void splitf16(float x0, float x1,
                                         uint32_t& h, uint32_t& l) {
    __half2 hh = __floats2half2_rn(x0, x1);
    float2 bk = __half22float2(hh);
    __half2 ll = __floats2half2_rn(x0 - bk.x, x1 - bk.y);
    h = *(uint32_t*)&hh;  l = *(uint32_t*)&ll;
}
__device__ __forceinline__ void mma_f16(float* d, uint32_t a0, uint32_t a1,
                                        uint32_t a2, uint32_t a3,
                                        uint32_t b0, uint32_t b1) {
    asm volatile(
        "mma.sync.aligned.m16n8k16.row.col.f32.f16.f16.f32 "
        "{%0,%1,%2,%3},{%4,%5,%6,%7},{%8,%9},{%0,%1,%2,%3};"
        : "+f"(d[0]), "+f"(d[1]), "+f"(d[2]), "+f"(d[3])
        : "r"(a0), "r"(a1), "r"(a2), "r"(a3), "r"(b0), "r"(b1));
}
__device__ __forceinline__ uint32_t swz(int row, uint32_t byteInRow) {
    return (uint32_t)(row * 64) + (byteInRow ^ (((uint32_t)(row >> 1) & 1u) << 5));
}
__device__ __forceinline__ uint32_t smem_u32(const void* p) {
    uint32_t a;
    asm("{ .reg .u64 t; cvta.to.shared.u64 t, %1; cvt.u32.u64 %0, t; }"
        : "=r"(a) : "l"(p));
    return a;
}
__device__ __forceinline__ void cpa16(uint32_t dst, const void* src) {
    asm volatile("cp.async.cg.shared.global [%0], [%1], 16;"
                 :: "r"(dst), "l"(src));
}
#define CPA_COMMIT() asm volatile("cp.async.commit_group;" ::: "memory")
#define CPA_WAIT0()  asm volatile("cp.async.wait_group 0;" ::: "memory")

// ===========================================================================
// Kernel 1: projections (fp32). 64r x 128n tile, 8x4 micro. f,g -> [n][q].
// ===========================================================================
__global__ __launch_bounds__(256) void proj_kernel(
    const float* __restrict__ x, const float* __restrict__ Wq,
    const float* __restrict__ Wk, const float* __restrict__ Wv)
{
    __shared__ float Ws[16 * 68];
    __shared__ float xs[16 * 128];
    const int b = blockIdx.z, r0 = blockIdx.y * 64, n0 = blockIdx.x * 128;
    const int tid = threadIdx.x;
    const int tx = tid & 31, ty = tid >> 5;
    const float* xb = x + (size_t)b * Cn * Nn;

    float acc[8][4] = {};

    for (int k0 = 0; k0 < Cn; k0 += 16) {
        {
            int rr = tid >> 2, k4 = tid & 3, r = r0 + rr;
            const float* Wsrc; int row;
            if (r < 32)      { Wsrc = Wq; row = r; }
            else if (r < 64) { Wsrc = Wk; row = r - 32; }
            else             { Wsrc = Wv; row = r - 64; }
            float4 wv = *(const float4*)&Wsrc[row * Cn + k0 + 4 * k4];
            Ws[(4 * k4 + 0) * 68 + rr] = wv.x;
            Ws[(4 * k4 + 1) * 68 + rr] = wv.y;
            Ws[(4 * k4 + 2) * 68 + rr] = wv.z;
            Ws[(4 * k4 + 3) * 68 + rr] = wv.w;
        }
        #pragma unroll
        for (int k = 0; k < 2; k++) {
            int idx = tid + 256 * k;
            int kk = idx >> 5, n4 = idx & 31;
            *(float4*)&xs[kk * 128 + 4 * n4] =
                *(const float4*)&xb[(size_t)(k0 + kk) * Nn + n0 + 4 * n4];
        }
        __syncthreads();

        #pragma unroll
        for (int kk = 0; kk < 16; kk++) {
            float4 a0 = *(const float4*)&Ws[kk * 68 + 8 * ty];
            float4 a1 = *(const float4*)&Ws[kk * 68 + 8 * ty + 4];
            float4 bb = *(const float4*)&xs[kk * 128 + 4 * tx];
            float a[8] = {a0.x, a0.y, a0.z, a0.w, a1.x, a1.y, a1.z, a1.w};
            float bv[4] = {bb.x, bb.y, bb.z, bb.w};
            #pragma unroll
            for (int i = 0; i < 8; i++)
                #pragma unroll
                for (int j = 0; j < 4; j++) acc[i][j] += a[i] * bv[j];
        }
        __syncthreads();
    }

    #pragma unroll
    for (int i = 0; i < 8; i++) {
        int r = r0 + 8 * ty + i;
        if (r < 64) {
            float* dst = (r < 32) ? (g_fT + (size_t)b * Nn * CQ + r)
                                  : (g_gT + (size_t)b * Nn * CQ + (r - 32));
            #pragma unroll
            for (int j = 0; j < 4; j++)
                dst[(size_t)(n0 + 4 * tx + j) * CQ] = acc[i][j];
        } else {
            *(float4*)&g_v[(size_t)b * Cn * Nn + (size_t)(r - 64) * Nn + n0 + 4 * tx]
                = make_float4(acc[i][0], acc[i][1], acc[i][2], acc[i][3]);
        }
    }
}

// ===========================================================================
// Kernel 1.5: fp32 -> fp16 (f single; g,v hi/lo split), pair-slot permuted.
// ===========================================================================
__global__ __launch_bounds__(256) void repack_kernel()
{
    int u = blockIdx.x * 256 + threadIdx.x;
    if (u < 262144) {
        int row = u >> 4, wd = u & 15;
        int kk = wd >> 3, s = wd & 7, w8 = ((s & 1) << 2) | (s >> 1);
        const float* src = g_fT + (size_t)row * 32 + kk * 16 + w8 * 2;
        g_fX[u] = packf16(src[0], src[1]);
    } else if (u < 524288) {
        int v = u - 262144;
        int row = v >> 4, wd = v & 15;
        int kk = wd >> 3, s = wd & 7, w8 = ((s & 1) << 2) | (s >> 1);
        const float* src = g_gT + (size_t)row * 32 + kk * 16 + w8 * 2;
        uint32_t h, l;
        splitf16(src[0], src[1], h, l);
        g_gH[v] = h; g_gL[v] = l;
    } else {
        int vv = u - 524288;
        int row = vv >> 11, w11 = vv & 2047;
        int it = w11 >> 4, wd = w11 & 15;
        int kk = wd >> 3, s = wd & 7, w8 = ((s & 1) << 2) | (s >> 1);
        const float* src = g_v + (size_t)row * 4096 + it * 32 + kk * 16 + w8 * 2;
        uint32_t h, l;
        splitf16(src[0], src[1], h, l);
        g_vH[vv] = h; g_vL[vv] = l;
    }
}

// ===========================================================================
// Kernel 2: fused attention, 2-term split-fp16 m16n8k16, cp.async
// double-buffered f/v tiles.
//   MMA1: s = (gh + gl) x f          (8 MMAs/warp/iter)
//   MMA2: o += (vh + vl) x e_fp16    (64 MMAs/warp/iter)
// ===========================================================================
static constexpr uint32_t BUF_SZ = 34816;              // f 2KB + vh/vl 32KB
static constexpr uint32_t IN_F = 0, IN_VH = 2048, IN_VL = 18432;
static constexpr uint32_t OF_GH = 69632, OF_GL = 73728;
static constexpr uint32_t OF_E  = 77824;
static constexpr uint32_t OF_DS = 81920, OF_INV = 82432;
static constexpr uint32_t SMEM_BYTES = 82688;

__device__ __forceinline__ void issue_copies(uint32_t sb, uint32_t bufbase,
                                             int b, int it, int tid)
{
    if (tid < 128) {  // f: 128 uint4 (2KB)
        int r = tid >> 2, q4 = tid & 3;
        const uint4* src = (const uint4*)g_fX
                         + (size_t)(b * 4096 + it * 32 + r) * 4 + q4;
        cpa16(sb + bufbase + IN_F + swz(r, q4 * 16), src);
    }
    #pragma unroll
    for (int k = 0; k < 8; k++) { // v: 2048 uint4 (vh+vl)
        int e = tid + 256 * k;
        int hl = e >> 10, idx = e & 1023;
        int r = idx >> 2, q4 = idx & 3;
        const uint4* src = (const uint4*)(hl ? g_vL : g_vH)
                         + (size_t)(b * 256 + r) * 512 + it * 4 + q4;
        cpa16(sb + bufbase + (hl ? IN_VL : IN_VH) + swz(r, q4 * 16), src);
    }
}

__global__ __launch_bounds__(256, 2) void attn_mma(float* __restrict__ out)
{
    extern __shared__ char sm[];
    const uint32_t sb = smem_u32(sm);
    const int tid = threadIdx.x, w = tid >> 5, lane = tid & 31;
    const int g = lane >> 2, t = lane & 3;
    const int jb = w & 3, ih = w >> 2;
    const int b = blockIdx.y, j0 = blockIdx.x * 64;

    // g tile (persistent): plain load once
    {
        const uint4* sH = (const uint4*)g_gH + (size_t)(b * 4096 + j0) * 4;
        const uint4* sL = (const uint4*)g_gL + (size_t)(b * 4096 + j0) * 4;
        int r = tid >> 2, q4 = tid & 3;
        *(uint4*)(sm + OF_GH + swz(r, q4 * 16)) = sH[tid];
        *(uint4*)(sm + OF_GL + swz(r, q4 * 16)) = sL[tid];
    }
    issue_copies(sb, 0, b, 0, tid);
    CPA_COMMIT();
    __syncthreads();

    // preload g A-fragments (persistent)
    uint2 gah[2][2], gal[2][2];
    #pragma unroll
    for (int kk = 0; kk < 2; kk++) {
        int r0 = 16 * jb + g;
        gah[kk][0] = *(const uint2*)(sm + OF_GH + swz(r0,     kk * 32 + 8 * t));
        gah[kk][1] = *(const uint2*)(sm + OF_GH + swz(r0 + 8, kk * 32 + 8 * t));
        gal[kk][0] = *(const uint2*)(sm + OF_GL + swz(r0,     kk * 32 + 8 * t));
        gal[kk][1] = *(const uint2*)(sm + OF_GL + swz(r0 + 8, kk * 32 + 8 * t));
    }

    float o[2][8][4] = {};
    float d0 = 0.f, d1 = 0.f;

    for (int it = 0; it < 128; it++) {
        CPA_WAIT0();
        __syncthreads();

        if (it + 1 < 128) {
            issue_copies(sb, ((it + 1) & 1) ? BUF_SZ : 0u, b, it + 1, tid);
            CPA_COMMIT();
        }
        const uint32_t vb = (it & 1) ? BUF_SZ : 0u;

        // ---- MMA1: S^T[j 16jb..+16][i 16ih..+16], 2-term -----------------
        float s[2][4] = {};
        #pragma unroll
        for (int kk = 0; kk < 2; kk++) {
            #pragma unroll
            for (int nt = 0; nt < 2; nt++) {
                int fr = 16 * ih + 8 * nt + g;
                uint2 fx = *(const uint2*)(sm + vb + IN_F + swz(fr, kk * 32 + 8 * t));
                mma_f16(s[nt], gah[kk][0].x, gah[kk][1].x, gah[kk][0].y, gah[kk][1].y, fx.x, fx.y);
                mma_f16(s[nt], gal[kk][0].x, gal[kk][1].x, gal[kk][0].y, gal[kk][1].y, fx.x, fx.y);
            }
        }
        // ---- exp, denom, pack e (single fp16) to smem --------------------
        #pragma unroll
        for (int nt = 0; nt < 2; nt++) {
            float e0 = __expf(s[nt][0] * 0.0625f), e1 = __expf(s[nt][1] * 0.0625f);
            float e2 = __expf(s[nt][2] * 0.0625f), e3 = __expf(s[nt][3] * 0.0625f);
            d0 += e0 + e1;  d1 += e2 + e3;
            uint32_t byte = (uint32_t)(ih * 32 + (2 * t + nt) * 4);
            int r0 = 16 * jb + g;
            *(uint32_t*)(sm + OF_E + swz(r0,     byte)) = packf16(e0, e1);
            *(uint32_t*)(sm + OF_E + swz(r0 + 8, byte)) = packf16(e2, e3);
        }
        __syncthreads();

        // ---- MMA2: o[c stripe 32w][64 j] += v e, K=32, 2-term ------------
        #pragma unroll
        for (int kk = 0; kk < 2; kk++) {
            uint2 vh[2][2], vl[2][2];
            #pragma unroll
            for (int mf = 0; mf < 2; mf++) {
                int r0 = 32 * w + 16 * mf + g;
                vh[mf][0] = *(const uint2*)(sm + vb + IN_VH + swz(r0,     kk * 32 + 8 * t));
                vh[mf][1] = *(const uint2*)(sm + vb + IN_VH + swz(r0 + 8, kk * 32 + 8 * t));
                vl[mf][0] = *(const uint2*)(sm + vb + IN_VL + swz(r0,     kk * 32 + 8 * t));
                vl[mf][1] = *(const uint2*)(sm + vb + IN_VL + swz(r0 + 8, kk * 32 + 8 * t));
            }
            #pragma unroll
            for (int nf = 0; nf < 8; nf++) {
                int er = 8 * nf + g;
                uint2 ex = *(const uint2*)(sm + OF_E + swz(er, kk * 32 + 8 * t));
                #pragma unroll
                for (int mf = 0; mf < 2; mf++) {
                    mma_f16(o[mf][nf], vh[mf][0].x, vh[mf][1].x, vh[mf][0].y, vh[mf][1].y, ex.x, ex.y);
                    mma_f16(o[mf][nf], vl[mf][0].x, vl[mf][1].x, vl[mf][0].y, vl[mf][1].y, ex.x, ex.y);
                }
            }
        }
    }

    // ---- denom reduce ----------------------------------------------------
    d0 += __shfl_xor_sync(~0u, d0, 1); d0 += __shfl_xor_sync(~0u, d0, 2);
    d1 += __shfl_xor_sync(~0u, d1, 1); d1 += __shfl_xor_sync(~0u, d1, 2);
    float* dS = (float*)(sm + OF_DS);
    if (t == 0) {
        dS[ih * 64 + 16 * jb + g]     = d0;
        dS[ih * 64 + 16 * jb + g + 8] = d1;
    }
    __syncthreads();
    float* invS = (float*)(sm + OF_INV);
    if (tid < 64) invS[tid] = 1.0f / (dS[tid] + dS[64 + tid]);
    __syncthreads();

    // ---- normalize + store ----------------------------------------------
    float* outB = out + (size_t)b * Cn * Nn;
    #pragma unroll
    for (int nf = 0; nf < 8; nf++) {
        float2 inv = *(const float2*)&invS[8 * nf + 2 * t];
        int j = j0 + 8 * nf + 2 * t;
        #pragma unroll
        for (int mf = 0; mf < 2; mf++) {
            int c0 = 32 * w + 16 * mf + g;
            *(float2*)&outB[(size_t)c0 * Nn + j] =
                make_float2(o[mf][nf][0] * inv.x, o[mf][nf][1] * inv.y);
            *(float2*)&outB[(size_t)(c0 + 8) * Nn + j] =
                make_float2(o[mf][nf][2] * inv.x, o[mf][nf][3] * inv.y);
        }
    }
}

// ===========================================================================
extern "C" void kernel_launch(void* const* d_in, const int* in_sizes, int n_in,
                              void* d_out, int out_size)
{
    const float* x  = (const float*)d_in[0];
    const float* Wq = (const float*)d_in[1];
    const float* Wk = (const float*)d_in[2];
    const float* Wv = (const float*)d_in[3];
    float* out = (float*)d_out;

    proj_kernel<<<dim3(Nn / 128, 5, Bn), 256>>>(x, Wq, Wk, Wv);
    repack_kernel<<<10240, 256>>>();

    cudaFuncSetAttribute(attn_mma,
                         cudaFuncAttributeMaxDynamicSharedMemorySize, SMEM_BYTES);
    attn_mma<<<dim3(Nn / 64, Bn), 256, SMEM_BYTES>>>(out);
}

// round 10
// speedup vs baseline: 2.3893x; 1.0024x over previous
#include <cuda_runtime.h>
#include <cuda_fp16.h>
#include <cstdint>

static constexpr int Bn = 4, Cn = 256, CQ = 32, Nn = 4096;

// fp32 proj outputs
__device__ float g_fT[Bn * Nn * CQ];   // [b][n][q]
__device__ float g_gT[Bn * Nn * CQ];   // [b][n][q]
__device__ float g_v [Bn * Cn * Nn];   // [b][c][n]
// fp16 packed (fp16x2 words, pair-slot permuted). f single, g/v hi+lo split.
__device__ uint32_t g_fX[262144];                   // row=b*4096+n, 16 words
__device__ uint32_t g_gH[262144],  g_gL[262144];
__device__ uint32_t g_vH[2097152], g_vL[2097152];   // row=b*256+c, 2048 words

// ---------------------------------------------------------------------------
__device__ __forceinline__ uint32_t packf16(float x0, float x1) {   // x0 -> low
    __half2 h = __floats2half2_rn(x0, x1);
    return *(uint32_t*)&h;
}
__device__ __forceinline__ void splitf16(float x0, float x1,
                                         uint32_t& h, uint32_t& l) {
    __half2 hh = __floats2half2_rn(x0, x1);
    float2 bk = __half22float2(hh);
    __half2 ll = __floats2half2_rn(x0 - bk.x, x1 - bk.y);
    h = *(uint32_t*)&hh;  l = *(uint32_t*)&ll;
}
__device__ __forceinline__ void mma_f16(float* d, uint32_t a0, uint32_t a1,
                                        uint32_t a2, uint32_t a3,
                                        uint32_t b0, uint32_t b1) {
    asm volatile(
        "mma.sync.aligned.m16n8k16.row.col.f32.f16.f16.f32 "
        "{%0,%1,%2,%3},{%4,%5,%6,%7},{%8,%9},{%0,%1,%2,%3};"
        : "+f"(d[0]), "+f"(d[1]), "+f"(d[2]), "+f"(d[3])
        : "r"(a0), "r"(a1), "r"(a2), "r"(a3), "r"(b0), "r"(b1));
}
__device__ __forceinline__ uint32_t swz(int row, uint32_t byteInRow) {
    return (uint32_t)(row * 64) + (byteInRow ^ (((uint32_t)(row >> 1) & 1u) << 5));
}
__device__ __forceinline__ uint32_t smem_u32(const void* p) {
    uint32_t a;
    asm("{ .reg .u64 t; cvta.to.shared.u64 t, %1; cvt.u32.u64 %0, t; }"
        : "=r"(a) : "l"(p));
    return a;
}
__device__ __forceinline__ void cpa16(uint32_t dst, const void* src) {
    asm volatile("cp.async.cg.shared.global [%0], [%1], 16;"
                 :: "r"(dst), "l"(src));
}
#define CPA_COMMIT() asm volatile("cp.async.commit_group;" ::: "memory")
#define CPA_WAIT0()  asm volatile("cp.async.wait_group 0;" ::: "memory")

// ===========================================================================
// Kernel 1: projections (fp32). 64r x 128n tile, 8x4 micro. f,g -> [n][q].
// ===========================================================================
__global__ __launch_bounds__(256) void proj_kernel(
    const float* __restrict__ x, const float* __restrict__ Wq,
    const float* __restrict__ Wk, const float* __restrict__ Wv)
{
    __shared__ float Ws[16 * 68];
    __shared__ float xs[16 * 128];
    const int b = blockIdx.z, r0 = blockIdx.y * 64, n0 = blockIdx.x * 128;
    const int tid = threadIdx.x;
    const int tx = tid & 31, ty = tid >> 5;
    const float* xb = x + (size_t)b * Cn * Nn;

    float acc[8][4] = {};

    for (int k0 = 0; k0 < Cn; k0 += 16) {
        {
            int rr = tid >> 2, k4 = tid & 3, r = r0 + rr;
            const float* Wsrc; int row;
            if (r < 32)      { Wsrc = Wq; row = r; }
            else if (r < 64) { Wsrc = Wk; row = r - 32; }
            else             { Wsrc = Wv; row = r - 64; }
            float4 wv = *(const float4*)&Wsrc[row * Cn + k0 + 4 * k4];
            Ws[(4 * k4 + 0) * 68 + rr] = wv.x;
            Ws[(4 * k4 + 1) * 68 + rr] = wv.y;
            Ws[(4 * k4 + 2) * 68 + rr] = wv.z;
            Ws[(4 * k4 + 3) * 68 + rr] = wv.w;
        }
        #pragma unroll
        for (int k = 0; k < 2; k++) {
            int idx = tid + 256 * k;
            int kk = idx >> 5, n4 = idx & 31;
            *(float4*)&xs[kk * 128 + 4 * n4] =
                *(const float4*)&xb[(size_t)(k0 + kk) * Nn + n0 + 4 * n4];
        }
        __syncthreads();

        #pragma unroll
        for (int kk = 0; kk < 16; kk++) {
            float4 a0 = *(const float4*)&Ws[kk * 68 + 8 * ty];
            float4 a1 = *(const float4*)&Ws[kk * 68 + 8 * ty + 4];
            float4 bb = *(const float4*)&xs[kk * 128 + 4 * tx];
            float a[8] = {a0.x, a0.y, a0.z, a0.w, a1.x, a1.y, a1.z, a1.w};
            float bv[4] = {bb.x, bb.y, bb.z, bb.w};
            #pragma unroll
            for (int i = 0; i < 8; i++)
                #pragma unroll
                for (int j = 0; j < 4; j++) acc[i][j] += a[i] * bv[j];
        }
        __syncthreads();
    }

    #pragma unroll
    for (int i = 0; i < 8; i++) {
        int r = r0 + 8 * ty + i;
        if (r < 64) {
            float* dst = (r < 32) ? (g_fT + (size_t)b * Nn * CQ + r)
                                  : (g_gT + (size_t)b * Nn * CQ + (r - 32));
            #pragma unroll
            for (int j = 0; j < 4; j++)
                dst[(size_t)(n0 + 4 * tx + j) * CQ] = acc[i][j];
        } else {
            *(float4*)&g_v[(size_t)b * Cn * Nn + (size_t)(r - 64) * Nn + n0 + 4 * tx]
                = make_float4(acc[i][0], acc[i][1], acc[i][2], acc[i][3]);
        }
    }
}

// ===========================================================================
// Kernel 1.5: fp32 -> fp16 (f single; g,v hi/lo split), pair-slot permuted.
// ===========================================================================
__global__ __launch_bounds__(256) void repack_kernel()
{
    int u = blockIdx.x * 256 + threadIdx.x;
    if (u < 262144) {
        int row = u >> 4, wd = u & 15;
        int kk = wd >> 3, s = wd & 7, w8 = ((s & 1) << 2) | (s >> 1);
        const float* src = g_fT + (size_t)row * 32 + kk * 16 + w8 * 2;
        g_fX[u] = packf16(src[0], src[1]);
    } else if (u < 524288) {
        int v = u - 262144;
        int row = v >> 4, wd = v & 15;
        int kk = wd >> 3, s = wd & 7, w8 = ((s & 1) << 2) | (s >> 1);
        const float* src = g_gT + (size_t)row * 32 + kk * 16 + w8 * 2;
        uint32_t h, l;
        splitf16(src[0], src[1], h, l);
        g_gH[v] = h; g_gL[v] = l;
    } else {
        int vv = u - 524288;
        int row = vv >> 11, w11 = vv & 2047;
        int it = w11 >> 4, wd = w11 & 15;
        int kk = wd >> 3, s = wd & 7, w8 = ((s & 1) << 2) | (s >> 1);
        const float* src = g_v + (size_t)row * 4096 + it * 32 + kk * 16 + w8 * 2;
        uint32_t h, l;
        splitf16(src[0], src[1], h, l);
        g_vH[vv] = h; g_vL[vv] = l;
    }
}

// ===========================================================================
// Kernel 2: fused attention, 2-term split-fp16 m16n8k16, cp.async
// double-buffered f/v tiles.
//   MMA1: s = (gh + gl) x f          (8 MMAs/warp/iter)
//   MMA2: o += (vh + vl) x e_fp16    (64 MMAs/warp/iter)
// ===========================================================================
static constexpr uint32_t BUF_SZ = 34816;              // f 2KB + vh/vl 32KB
static constexpr uint32_t IN_F = 0, IN_VH = 2048, IN_VL = 18432;
static constexpr uint32_t OF_GH = 69632, OF_GL = 73728;
static constexpr uint32_t OF_E  = 77824;
static constexpr uint32_t OF_DS = 81920, OF_INV = 82432;
static constexpr uint32_t SMEM_BYTES = 82688;

__device__ __forceinline__ void issue_copies(uint32_t sb, uint32_t bufbase,
                                             int b, int it, int tid)
{
    if (tid < 128) {  // f: 128 uint4 (2KB)
        int r = tid >> 2, q4 = tid & 3;
        const uint4* src = (const uint4*)g_fX
                         + (size_t)(b * 4096 + it * 32 + r) * 4 + q4;
        cpa16(sb + bufbase + IN_F + swz(r, q4 * 16), src);
    }
    #pragma unroll
    for (int k = 0; k < 8; k++) { // v: 2048 uint4 (vh+vl)
        int e = tid + 256 * k;
        int hl = e >> 10, idx = e & 1023;
        int r = idx >> 2, q4 = idx & 3;
        const uint4* src = (const uint4*)(hl ? g_vL : g_vH)
                         + (size_t)(b * 256 + r) * 512 + it * 4 + q4;
        cpa16(sb + bufbase + (hl ? IN_VL : IN_VH) + swz(r, q4 * 16), src);
    }
}

__global__ __launch_bounds__(256, 2) void attn_mma(float* __restrict__ out)
{
    extern __shared__ char sm[];
    const uint32_t sb = smem_u32(sm);
    const int tid = threadIdx.x, w = tid >> 5, lane = tid & 31;
    const int g = lane >> 2, t = lane & 3;
    const int jb = w & 3, ih = w >> 2;
    const int b = blockIdx.y, j0 = blockIdx.x * 64;

    // g tile (persistent): plain load once
    {
        const uint4* sH = (const uint4*)g_gH + (size_t)(b * 4096 + j0) * 4;
        const uint4* sL = (const uint4*)g_gL + (size_t)(b * 4096 + j0) * 4;
        int r = tid >> 2, q4 = tid & 3;
        *(uint4*)(sm + OF_GH + swz(r, q4 * 16)) = sH[tid];
        *(uint4*)(sm + OF_GL + swz(r, q4 * 16)) = sL[tid];
    }
    issue_copies(sb, 0, b, 0, tid);
    CPA_COMMIT();
    __syncthreads();

    // preload g A-fragments (persistent)
    uint2 gah[2][2], gal[2][2];
    #pragma unroll
    for (int kk = 0; kk < 2; kk++) {
        int r0 = 16 * jb + g;
        gah[kk][0] = *(const uint2*)(sm + OF_GH + swz(r0,     kk * 32 + 8 * t));
        gah[kk][1] = *(const uint2*)(sm + OF_GH + swz(r0 + 8, kk * 32 + 8 * t));
        gal[kk][0] = *(const uint2*)(sm + OF_GL + swz(r0,     kk * 32 + 8 * t));
        gal[kk][1] = *(const uint2*)(sm + OF_GL + swz(r0 + 8, kk * 32 + 8 * t));
    }

    float o[2][8][4] = {};
    float d0 = 0.f, d1 = 0.f;

    for (int it = 0; it < 128; it++) {
        CPA_WAIT0();
        __syncthreads();

        if (it + 1 < 128) {
            issue_copies(sb, ((it + 1) & 1) ? BUF_SZ : 0u, b, it + 1, tid);
            CPA_COMMIT();
        }
        const uint32_t vb = (it & 1) ? BUF_SZ : 0u;

        // ---- MMA1: S^T[j 16jb..+16][i 16ih..+16], 2-term -----------------
        float s[2][4] = {};
        #pragma unroll
        for (int kk = 0; kk < 2; kk++) {
            #pragma unroll
            for (int nt = 0; nt < 2; nt++) {
                int fr = 16 * ih + 8 * nt + g;
                uint2 fx = *(const uint2*)(sm + vb + IN_F + swz(fr, kk * 32 + 8 * t));
                mma_f16(s[nt], gah[kk][0].x, gah[kk][1].x, gah[kk][0].y, gah[kk][1].y, fx.x, fx.y);
                mma_f16(s[nt], gal[kk][0].x, gal[kk][1].x, gal[kk][0].y, gal[kk][1].y, fx.x, fx.y);
            }
        }
        // ---- exp, denom, pack e (single fp16) to smem --------------------
        #pragma unroll
        for (int nt = 0; nt < 2; nt++) {
            float e0 = __expf(s[nt][0] * 0.0625f), e1 = __expf(s[nt][1] * 0.0625f);
            float e2 = __expf(s[nt][2] * 0.0625f), e3 = __expf(s[nt][3] * 0.0625f);
            d0 += e0 + e1;  d1 += e2 + e3;
            uint32_t byte = (uint32_t)(ih * 32 + (2 * t + nt) * 4);
            int r0 = 16 * jb + g;
            *(uint32_t*)(sm + OF_E + swz(r0,     byte)) = packf16(e0, e1);
            *(uint32_t*)(sm + OF_E + swz(r0 + 8, byte)) = packf16(e2, e3);
        }
        __syncthreads();

        // ---- MMA2: o[c stripe 32w][64 j] += v e, K=32, 2-term ------------
        #pragma unroll
        for (int kk = 0; kk < 2; kk++) {
            uint2 vh[2][2], vl[2][2];
            #pragma unroll
            for (int mf = 0; mf < 2; mf++) {
                int r0 = 32 * w + 16 * mf + g;
                vh[mf][0] = *(const uint2*)(sm + vb + IN_VH + swz(r0,     kk * 32 + 8 * t));
                vh[mf][1] = *(const uint2*)(sm + vb + IN_VH + swz(r0 + 8, kk * 32 + 8 * t));
                vl[mf][0] = *(const uint2*)(sm + vb + IN_VL + swz(r0,     kk * 32 + 8 * t));
                vl[mf][1] = *(const uint2*)(sm + vb + IN_VL + swz(r0 + 8, kk * 32 + 8 * t));
            }
            #pragma unroll
            for (int nf = 0; nf < 8; nf++) {
                int er = 8 * nf + g;
                uint2 ex = *(const uint2*)(sm + OF_E + swz(er, kk * 32 + 8 * t));
                #pragma unroll
                for (int mf = 0; mf < 2; mf++) {
                    mma_f16(o[mf][nf], vh[mf][0].x, vh[mf][1].x, vh[mf][0].y, vh[mf][1].y, ex.x, ex.y);
                    mma_f16(o[mf][nf], vl[mf][0].x, vl[mf][1].x, vl[mf][0].y, vl[mf][1].y, ex.x, ex.y);
                }
            }
        }
    }

    // ---- denom reduce ----------------------------------------------------
    d0 += __shfl_xor_sync(~0u, d0, 1); d0 += __shfl_xor_sync(~0u, d0, 2);
    d1 += __shfl_xor_sync(~0u, d1, 1); d1 += __shfl_xor_sync(~0u, d1, 2);
    float* dS = (float*)(sm + OF_DS);
    if (t == 0) {
        dS[ih * 64 + 16 * jb + g]     = d0;
        dS[ih * 64 + 16 * jb + g + 8] = d1;
    }
    __syncthreads();
    float* invS = (float*)(sm + OF_INV);
    if (tid < 64) invS[tid] = 1.0f / (dS[tid] + dS[64 + tid]);
    __syncthreads();

    // ---- normalize + store ----------------------------------------------
    float* outB = out + (size_t)b * Cn * Nn;
    #pragma unroll
    for (int nf = 0; nf < 8; nf++) {
        float2 inv = *(const float2*)&invS[8 * nf + 2 * t];
        int j = j0 + 8 * nf + 2 * t;
        #pragma unroll
        for (int mf = 0; mf < 2; mf++) {
            int c0 = 32 * w + 16 * mf + g;
            *(float2*)&outB[(size_t)c0 * Nn + j] =
                make_float2(o[mf][nf][0] * inv.x, o[mf][nf][1] * inv.y);
            *(float2*)&outB[(size_t)(c0 + 8) * Nn + j] =
                make_float2(o[mf][nf][2] * inv.x, o[mf][nf][3] * inv.y);
        }
    }
}

// ===========================================================================
extern "C" void kernel_launch(void* const* d_in, const int* in_sizes, int n_in,
                              void* d_out, int out_size)
{
    const float* x  = (const float*)d_in[0];
    const float* Wq = (const float*)d_in[1];
    const float* Wk = (const float*)d_in[2];
    const float* Wv = (const float*)d_in[3];
    float* out = (float*)d_out;

    proj_kernel<<<dim3(Nn / 128, 5, Bn), 256>>>(x, Wq, Wk, Wv);
    repack_kernel<<<10240, 256>>>();

    cudaFuncSetAttribute(attn_mma,
                         cudaFuncAttributeMaxDynamicSharedMemorySize, SMEM_BYTES);
    attn_mma<<<dim3(Nn / 64, Bn), 256, SMEM_BYTES>>>(out);
}